// round 1
// baseline (speedup 1.0000x reference)
#include <cuda_runtime.h>
#include <math.h>

#define Bn 2
#define Ln 2048
#define Dn 2048
#define Hn 16
#define DHn 128
#define MROWS (Bn*Ln)          // 4096
#define MAXPOS 4096

// ---------------- scratch (device globals; no allocation allowed) ----------
__device__ float g_Q[(size_t)Bn*Hn*Ln*DHn];   // [b][h][l][dh]
__device__ float g_K[(size_t)Bn*Hn*Ln*DHn];
__device__ float g_V[(size_t)Bn*Hn*Ln*DHn];
__device__ float g_O[(size_t)Bn*Ln*Dn];       // attention output, head-concat
__device__ float g_cos[MAXPOS*64];
__device__ float g_sin[MAXPOS*64];

// ---------------- RoPE tables (fp32 path mimics the numpy reference) -------
__global__ void build_rope_tables() {
    int idx = blockIdx.x * blockDim.x + threadIdx.x;
    if (idx >= MAXPOS*64) return;
    int pos = idx >> 6;
    int i   = idx & 63;
    float expo = (float)(2*i) * (1.0f/128.0f);
    float inv  = 1.0f / powf(10000.0f, expo);
    float ang  = (float)pos * inv;
    g_cos[idx] = cosf(ang);
    g_sin[idx] = sinf(ang);
}

// ---------------- RoPE apply on Q and K in place ----------------------------
__global__ void rope_apply(const int* __restrict__ tp) {
    int idx = blockIdx.x*blockDim.x + threadIdx.x;
    const int total = Bn*Hn*Ln*64;
    if (idx >= total) return;
    int i = idx & 63;
    int l = (idx >> 6) & (Ln-1);
    int h = (idx >> 17) & (Hn-1);
    int b = idx >> 21;
    int pos = tp[b*Ln + l];
    float c = g_cos[pos*64 + i];
    float s = g_sin[pos*64 + i];
    size_t off = ((((size_t)b*Hn + h)*Ln + l)*DHn) + 2*i;
    float2 q = *(float2*)&g_Q[off];
    *(float2*)&g_Q[off] = make_float2(q.x*c - q.y*s, q.x*s + q.y*c);
    float2 k = *(float2*)&g_K[off];
    *(float2*)&g_K[off] = make_float2(k.x*c - k.y*s, k.x*s + k.y*c);
}

// ---------------- SGEMM: C[m,n] = sum_k A[m,k]*W[n,k] ----------------------
// A: [M=4096, K=2048] row-major.  W: [N=2048, K=2048] row-major.
// MODE 0: C row-major [M, Dn].  MODE 1: scatter to [b][h][l][dh] QKV layout.
template<int MODE>
__global__ __launch_bounds__(256)
void sgemm_k(const float* __restrict__ A, const float* __restrict__ W,
             float* __restrict__ C) {
    __shared__ float As[8][128];
    __shared__ float Bs[8][128];
    const int K = Dn;
    int tid = threadIdx.x;
    int tx = tid & 15, ty = tid >> 4;
    const float* Ab = A + (size_t)blockIdx.y * 128 * K;
    const float* Wb = W + (size_t)blockIdx.x * 128 * K;
    int lrow = tid >> 1;
    int lcol = (tid & 1) << 2;

    float acc[8][8];
    #pragma unroll
    for (int i = 0; i < 8; i++)
        #pragma unroll
        for (int j = 0; j < 8; j++) acc[i][j] = 0.f;

    for (int k0 = 0; k0 < K; k0 += 8) {
        float4 av = *(const float4*)&Ab[(size_t)lrow*K + k0 + lcol];
        float4 wv = *(const float4*)&Wb[(size_t)lrow*K + k0 + lcol];
        __syncthreads();
        As[lcol+0][lrow]=av.x; As[lcol+1][lrow]=av.y; As[lcol+2][lrow]=av.z; As[lcol+3][lrow]=av.w;
        Bs[lcol+0][lrow]=wv.x; Bs[lcol+1][lrow]=wv.y; Bs[lcol+2][lrow]=wv.z; Bs[lcol+3][lrow]=wv.w;
        __syncthreads();
        #pragma unroll
        for (int kk = 0; kk < 8; kk++) {
            float a[8], bb[8];
            *(float4*)(a)    = *(const float4*)&As[kk][ty*8];
            *(float4*)(a+4)  = *(const float4*)&As[kk][ty*8+4];
            *(float4*)(bb)   = *(const float4*)&Bs[kk][tx*8];
            *(float4*)(bb+4) = *(const float4*)&Bs[kk][tx*8+4];
            #pragma unroll
            for (int i = 0; i < 8; i++)
                #pragma unroll
                for (int j = 0; j < 8; j++) acc[i][j] += a[i]*bb[j];
        }
    }

    int mBase = blockIdx.y*128 + ty*8;
    int nBase = blockIdx.x*128 + tx*8;
    #pragma unroll
    for (int i = 0; i < 8; i++) {
        int m = mBase + i;
        float4 v0 = make_float4(acc[i][0],acc[i][1],acc[i][2],acc[i][3]);
        float4 v1 = make_float4(acc[i][4],acc[i][5],acc[i][6],acc[i][7]);
        if (MODE == 0) {
            size_t off = (size_t)m*Dn + nBase;
            *(float4*)&C[off]   = v0;
            *(float4*)&C[off+4] = v1;
        } else {
            int b = m >> 11, l = m & (Ln-1);
            int h = nBase >> 7, dh = nBase & 127;
            size_t off = ((((size_t)b*Hn + h)*Ln + l)*DHn) + dh;
            *(float4*)&C[off]   = v0;
            *(float4*)&C[off+4] = v1;
        }
    }
}

// ---------------- causal flash attention, fp32 ------------------------------
// Grid: (L/64, B*H). 256 threads = 16x16. Thread (ty,tx):
//   S tile:  rows ty*4..+3, cols tx*4..+3 of the 64x64 score tile
//   O accum: rows ty*4..+3, cols tx*8..+7 of [64][128]
// m/l kept per-lane redundantly (consistent via 16-lane shuffle reduces).
__global__ __launch_bounds__(256)
void attn_k(const float* __restrict__ Qg, const float* __restrict__ Kg,
            const float* __restrict__ Vg, float* __restrict__ Og) {
    extern __shared__ float smem[];
    float* sQ = smem;                 // 64 x 132
    float* sK = sQ + 64*132;          // 64 x 132
    float* sV = sK + 64*132;          // 64 x 132
    float* sP = sV + 64*132;          // 64 x 68

    int tid = threadIdx.x;
    int tx = tid & 15, ty = tid >> 4;
    int qb = blockIdx.x;
    int bh = blockIdx.y;
    const float* Qp = Qg + ((size_t)bh*Ln + (size_t)qb*64)*DHn;
    const float* Kp = Kg + (size_t)bh*Ln*DHn;
    const float* Vp = Vg + (size_t)bh*Ln*DHn;

    // load Q tile (stays resident)
    for (int c = tid; c < 64*32; c += 256) {
        int r = c >> 5, c4 = (c & 31) << 2;
        *(float4*)&sQ[r*132 + c4] = *(const float4*)&Qp[(size_t)r*DHn + c4];
    }

    float o[4][8];
    #pragma unroll
    for (int r = 0; r < 4; r++)
        #pragma unroll
        for (int c = 0; c < 8; c++) o[r][c] = 0.f;
    float mrow[4] = {-1e30f,-1e30f,-1e30f,-1e30f};
    float lrow[4] = {0.f,0.f,0.f,0.f};
    const float scale = 0.08838834764831845f;  // 1/sqrt(128)

    for (int kb = 0; kb <= qb; kb++) {
        __syncthreads();   // previous PV / Q-load done before K,V overwrite
        for (int c = tid; c < 64*32; c += 256) {
            int r = c >> 5, c4 = (c & 31) << 2;
            size_t goff = ((size_t)kb*64 + r)*DHn + c4;
            *(float4*)&sK[r*132 + c4] = *(const float4*)&Kp[goff];
            *(float4*)&sV[r*132 + c4] = *(const float4*)&Vp[goff];
        }
        __syncthreads();

        // S = Q K^T (64x64, 4x4 per thread)
        float s[4][4];
        #pragma unroll
        for (int r = 0; r < 4; r++)
            #pragma unroll
            for (int j = 0; j < 4; j++) s[r][j] = 0.f;
        #pragma unroll 8
        for (int d = 0; d < 128; d += 4) {
            float4 q4[4], k4[4];
            #pragma unroll
            for (int r = 0; r < 4; r++) q4[r] = *(const float4*)&sQ[(ty*4+r)*132 + d];
            #pragma unroll
            for (int j = 0; j < 4; j++) k4[j] = *(const float4*)&sK[(tx*4+j)*132 + d];
            #pragma unroll
            for (int r = 0; r < 4; r++)
                #pragma unroll
                for (int j = 0; j < 4; j++)
                    s[r][j] += q4[r].x*k4[j].x + q4[r].y*k4[j].y
                             + q4[r].z*k4[j].z + q4[r].w*k4[j].w;
        }

        // scale + causal mask + online softmax
        bool diag = (kb == qb);
        float rmax[4], fac[4], rsum[4];
        #pragma unroll
        for (int r = 0; r < 4; r++) {
            #pragma unroll
            for (int j = 0; j < 4; j++) {
                float v = s[r][j]*scale;
                if (diag && (tx*4+j) > (ty*4+r)) v = -1e30f;
                s[r][j] = v;
            }
            rmax[r] = fmaxf(fmaxf(s[r][0],s[r][1]), fmaxf(s[r][2],s[r][3]));
        }
        #pragma unroll
        for (int off = 8; off > 0; off >>= 1)
            #pragma unroll
            for (int r = 0; r < 4; r++)
                rmax[r] = fmaxf(rmax[r], __shfl_xor_sync(0xffffffffu, rmax[r], off));
        #pragma unroll
        for (int r = 0; r < 4; r++) {
            float mN = fmaxf(mrow[r], rmax[r]);
            fac[r] = expf(mrow[r] - mN);
            mrow[r] = mN;
            float rs = 0.f;
            #pragma unroll
            for (int j = 0; j < 4; j++) {
                float p = expf(s[r][j] - mN);
                s[r][j] = p;
                rs += p;
            }
            rsum[r] = rs;
        }
        #pragma unroll
        for (int off = 8; off > 0; off >>= 1)
            #pragma unroll
            for (int r = 0; r < 4; r++)
                rsum[r] += __shfl_xor_sync(0xffffffffu, rsum[r], off);
        #pragma unroll
        for (int r = 0; r < 4; r++) lrow[r] = lrow[r]*fac[r] + rsum[r];

        // publish P
        #pragma unroll
        for (int r = 0; r < 4; r++)
            #pragma unroll
            for (int j = 0; j < 4; j++)
                sP[(ty*4+r)*68 + tx*4+j] = s[r][j];
        __syncthreads();

        // O = O*fac + P V
        #pragma unroll
        for (int r = 0; r < 4; r++)
            #pragma unroll
            for (int c = 0; c < 8; c++) o[r][c] *= fac[r];
        #pragma unroll 4
        for (int j = 0; j < 64; j++) {
            float pv[4];
            #pragma unroll
            for (int r = 0; r < 4; r++) pv[r] = sP[(ty*4+r)*68 + j];
            float4 v0 = *(const float4*)&sV[j*132 + tx*8];
            float4 v1 = *(const float4*)&sV[j*132 + tx*8 + 4];
            #pragma unroll
            for (int r = 0; r < 4; r++) {
                o[r][0]+=pv[r]*v0.x; o[r][1]+=pv[r]*v0.y; o[r][2]+=pv[r]*v0.z; o[r][3]+=pv[r]*v0.w;
                o[r][4]+=pv[r]*v1.x; o[r][5]+=pv[r]*v1.y; o[r][6]+=pv[r]*v1.z; o[r][7]+=pv[r]*v1.w;
            }
        }
    }

    // normalize + write to [B, L, D] with head-concat columns
    int b = bh >> 4, h = bh & 15;
    #pragma unroll
    for (int r = 0; r < 4; r++) {
        float inv = 1.0f / lrow[r];
        int l = qb*64 + ty*4 + r;
        size_t off = ((size_t)b*Ln + l)*Dn + h*128 + tx*8;
        float4 v0 = make_float4(o[r][0]*inv,o[r][1]*inv,o[r][2]*inv,o[r][3]*inv);
        float4 v1 = make_float4(o[r][4]*inv,o[r][5]*inv,o[r][6]*inv,o[r][7]*inv);
        *(float4*)&Og[off]   = v0;
        *(float4*)&Og[off+4] = v1;
    }
}

// ---------------- launch -----------------------------------------------------
extern "C" void kernel_launch(void* const* d_in, const int* in_sizes, int n_in,
                              void* d_out, int out_size) {
    const float* x  = (const float*)d_in[0];
    // d_in[1] = mask (tril causal) — causality handled analytically
    const int*   tp = (const int*)d_in[2];
    const float* Wq = (const float*)d_in[3];
    const float* Wk = (const float*)d_in[4];
    const float* Wv = (const float*)d_in[5];
    const float* Wo = (const float*)d_in[6];
    float* out = (float*)d_out;

    float *Qp, *Kp, *Vp, *Op;
    cudaGetSymbolAddress((void**)&Qp, g_Q);
    cudaGetSymbolAddress((void**)&Kp, g_K);
    cudaGetSymbolAddress((void**)&Vp, g_V);
    cudaGetSymbolAddress((void**)&Op, g_O);

    const int smem_attn = (3*64*132 + 64*68) * (int)sizeof(float);  // 118784 B
    cudaFuncSetAttribute((const void*)attn_k,
                         cudaFuncAttributeMaxDynamicSharedMemorySize, smem_attn);

    build_rope_tables<<<(MAXPOS*64 + 255)/256, 256>>>();

    dim3 gg(Dn/128, MROWS/128);
    sgemm_k<1><<<gg, 256>>>(x, Wq, Qp);
    sgemm_k<1><<<gg, 256>>>(x, Wk, Kp);
    sgemm_k<1><<<gg, 256>>>(x, Wv, Vp);

    const int rt = Bn*Hn*Ln*64;
    rope_apply<<<(rt + 255)/256, 256>>>(tp);

    attn_k<<<dim3(Ln/64, Bn*Hn), 256, smem_attn>>>(Qp, Kp, Vp, Op);

    sgemm_k<0><<<gg, 256>>>(Op, Wo, out);
}

// round 3
// speedup vs baseline: 1.5468x; 1.5468x over previous
#include <cuda_runtime.h>
#include <cuda_bf16.h>
#include <math.h>
#include <stdint.h>

#define Bn 2
#define Ln 2048
#define Dn 2048
#define Hn 16
#define DHn 128
#define MROWS (Bn*Ln)          // 4096
#define MAXPOS 4096

// ---------------- scratch (device globals; no allocation allowed) ----------
__device__ float g_Q[(size_t)MROWS*Dn];
__device__ float g_K[(size_t)MROWS*Dn];
__device__ float g_V[(size_t)MROWS*Dn];
__device__ __nv_bfloat16 g_xh[(size_t)MROWS*Dn];
__device__ __nv_bfloat16 g_xl[(size_t)MROWS*Dn];
__device__ __nv_bfloat16 g_wh[4][(size_t)Dn*Dn];
__device__ __nv_bfloat16 g_wl[4][(size_t)Dn*Dn];
__device__ __nv_bfloat16 g_Oh[(size_t)MROWS*Dn];
__device__ __nv_bfloat16 g_Ol[(size_t)MROWS*Dn];
__device__ float g_cos[MAXPOS*64];
__device__ float g_sin[MAXPOS*64];

// ======================= helpers ============================================
__device__ __forceinline__ uint32_t smem_u32(const void* p){
    uint32_t a;
    asm("{ .reg .u64 t; cvta.to.shared.u64 t, %1; cvt.u32.u64 %0, t; }" : "=r"(a) : "l"(p));
    return a;
}
__device__ __forceinline__ void cp16(uint32_t s, const void* g){
    asm volatile("cp.async.cg.shared.global [%0], [%1], 16;" :: "r"(s), "l"(g));
}
__device__ __forceinline__ void ldsm4(uint32_t* r, uint32_t a){
    asm volatile("ldmatrix.sync.aligned.m8n8.x4.shared.b16 {%0,%1,%2,%3},[%4];"
        : "=r"(r[0]),"=r"(r[1]),"=r"(r[2]),"=r"(r[3]) : "r"(a));
}
__device__ __forceinline__ void mma16816(float* c, const uint32_t* a, uint32_t b0, uint32_t b1){
    asm volatile("mma.sync.aligned.m16n8k16.row.col.f32.bf16.bf16.f32 "
        "{%0,%1,%2,%3},{%4,%5,%6,%7},{%8,%9},{%0,%1,%2,%3};"
        : "+f"(c[0]),"+f"(c[1]),"+f"(c[2]),"+f"(c[3])
        : "r"(a[0]),"r"(a[1]),"r"(a[2]),"r"(a[3]),"r"(b0),"r"(b1));
}
__device__ __forceinline__ uint32_t pack2(__nv_bfloat16 a, __nv_bfloat16 b){
    return ((uint32_t)__bfloat16_as_ushort(b)<<16) | (uint32_t)__bfloat16_as_ushort(a);
}

// ======================= split prep: f32 -> hi/lo bf16 ======================
__global__ void split_prep(const float* __restrict__ src,
                           __nv_bfloat16* __restrict__ h, __nv_bfloat16* __restrict__ l, int n4){
    int i = blockIdx.x*blockDim.x + threadIdx.x;
    if (i >= n4) return;
    float4 v = ((const float4*)src)[i];
    __nv_bfloat16 h0=__float2bfloat16(v.x), h1=__float2bfloat16(v.y),
                  h2=__float2bfloat16(v.z), h3=__float2bfloat16(v.w);
    __nv_bfloat16 l0=__float2bfloat16(v.x-__bfloat162float(h0));
    __nv_bfloat16 l1=__float2bfloat16(v.y-__bfloat162float(h1));
    __nv_bfloat16 l2=__float2bfloat16(v.z-__bfloat162float(h2));
    __nv_bfloat16 l3=__float2bfloat16(v.w-__bfloat162float(h3));
    ((uint2*)h)[i] = make_uint2(pack2(h0,h1), pack2(h2,h3));
    ((uint2*)l)[i] = make_uint2(pack2(l0,l1), pack2(l2,l3));
}

// ======================= split-bf16 mma.sync GEMM ===========================
// C[m,n] = sum_k A[m,k]*W[n,k], K=2048. A rows = 4096, W rows = 2048.
// A,W given as hi/lo bf16. CTA 128x256, BK=32, 8 warps (2x4), warp tile 64x64.
// 3-term: Ah*Wh + Ah*Wl + Al*Wh. fp32 accum.
#define SA_L_OFF 10240
#define SW_H_OFF 20480
#define SW_L_OFF 40960
#define STAGE_B  61440
#define G_SMEM   (3*STAGE_B)   // 184320

__global__ __launch_bounds__(256)
void gemm_mma(const __nv_bfloat16* __restrict__ Ah, const __nv_bfloat16* __restrict__ Al,
              const __nv_bfloat16* __restrict__ W0h, const __nv_bfloat16* __restrict__ W0l,
              const __nv_bfloat16* __restrict__ W1h, const __nv_bfloat16* __restrict__ W1l,
              const __nv_bfloat16* __restrict__ W2h, const __nv_bfloat16* __restrict__ W2l,
              float* __restrict__ C0, float* __restrict__ C1, float* __restrict__ C2)
{
    extern __shared__ char smem[];
    uint32_t sb = smem_u32(smem);
    const int tid = threadIdx.x, wid = tid>>5, lane = tid&31;
    const int z = blockIdx.z;
    const __nv_bfloat16* Wh = (z==0)?W0h:((z==1)?W1h:W2h);
    const __nv_bfloat16* Wl = (z==0)?W0l:((z==1)?W1l:W2l);
    float* C = (z==0)?C0:((z==1)?C1:C2);
    const int m0 = blockIdx.y*128, n0 = blockIdx.x*256;
    const int warp_m = (wid>>2)*64, warp_n = (wid&3)*64;

    // issue cp.async loads of k-chunk kt into stage st
    auto load_stage = [&](int st, int kt){
        uint32_t sbase = sb + st*STAGE_B;
        #pragma unroll
        for (int j=0;j<12;j++){
            int c = tid + j*256;
            uint32_t dst; const char* src;
            if (c < 1024){
                int cc = c & 511; int row = cc>>2, seg = cc&3;
                const char* base = (c<512)? (const char*)Ah : (const char*)Al;
                src = base + (((size_t)(m0+row)*Dn + kt*32)<<1) + seg*16;
                dst = sbase + ((c<512)?0u:(uint32_t)SA_L_OFF) + row*80 + seg*16;
            } else {
                int cc = (c-1024) & 1023; int row = cc>>2, seg = cc&3;
                const char* base = (c<2048)? (const char*)Wh : (const char*)Wl;
                src = base + (((size_t)(n0+row)*Dn + kt*32)<<1) + seg*16;
                dst = sbase + ((c<2048)?(uint32_t)SW_H_OFF:(uint32_t)SW_L_OFF) + row*80 + seg*16;
            }
            cp16(dst, src);
        }
    };

    float acc[4][8][4];
    #pragma unroll
    for (int i=0;i<4;i++)
        #pragma unroll
        for (int j=0;j<8;j++)
            #pragma unroll
            for (int q=0;q<4;q++) acc[i][j][q]=0.f;

    load_stage(0, 0);
    asm volatile("cp.async.commit_group;");
    load_stage(1, 1);
    asm volatile("cp.async.commit_group;");

    const int lrow = lane & 15;
    const uint32_t lcolB = (uint32_t)((lane>>4)<<4);   // 0 or 16 bytes (8 bf16)

    for (int kt=0; kt<64; ++kt){
        int st = kt - (kt/3)*3;
        uint32_t base = sb + st*STAGE_B;
        asm volatile("cp.async.wait_group 1;");
        __syncthreads();

        #pragma unroll
        for (int ks=0; ks<2; ++ks){
            uint32_t kB = ks*32;   // 16 bf16 = 32 bytes
            uint32_t aAddr = base + (uint32_t)(warp_m + lrow)*80 + lcolB + kB;
            uint32_t wAddr = base + SW_H_OFF + (uint32_t)(warp_n + lrow)*80 + lcolB + kB;

            uint32_t ahr[4][4], whr[4][4];
            #pragma unroll
            for (int mt=0; mt<4; mt++) ldsm4(ahr[mt], aAddr + mt*(16*80));
            #pragma unroll
            for (int p=0; p<4; p++)   ldsm4(whr[p], wAddr + p*(16*80));
            // hi*hi  (b-frag: even ntile = {r0,r2}, odd = {r1,r3})
            #pragma unroll
            for (int mt=0; mt<4; mt++)
                #pragma unroll
                for (int p=0; p<4; p++){
                    mma16816(acc[mt][2*p],   ahr[mt], whr[p][0], whr[p][2]);
                    mma16816(acc[mt][2*p+1], ahr[mt], whr[p][1], whr[p][3]);
                }
            // hi*lo
            {
                uint32_t wlr[4][4];
                #pragma unroll
                for (int p=0; p<4; p++) ldsm4(wlr[p], wAddr + (SW_L_OFF-SW_H_OFF) + p*(16*80));
                #pragma unroll
                for (int mt=0; mt<4; mt++)
                    #pragma unroll
                    for (int p=0; p<4; p++){
                        mma16816(acc[mt][2*p],   ahr[mt], wlr[p][0], wlr[p][2]);
                        mma16816(acc[mt][2*p+1], ahr[mt], wlr[p][1], wlr[p][3]);
                    }
            }
            // lo*hi
            {
                uint32_t alr[4][4];
                #pragma unroll
                for (int mt=0; mt<4; mt++) ldsm4(alr[mt], aAddr + SA_L_OFF + mt*(16*80));
                #pragma unroll
                for (int mt=0; mt<4; mt++)
                    #pragma unroll
                    for (int p=0; p<4; p++){
                        mma16816(acc[mt][2*p],   alr[mt], whr[p][0], whr[p][2]);
                        mma16816(acc[mt][2*p+1], alr[mt], whr[p][1], whr[p][3]);
                    }
            }
        }

        if (kt+2 < 64){
            int st2 = (kt+2) - ((kt+2)/3)*3;
            load_stage(st2, kt+2);
        }
        asm volatile("cp.async.commit_group;");
        __syncthreads();
    }

    // epilogue: direct fp32 stores
    const int row0 = m0 + warp_m + (lane>>2);
    const int col0 = n0 + warp_n + ((lane&3)<<1);
    #pragma unroll
    for (int mt=0; mt<4; mt++){
        #pragma unroll
        for (int nt=0; nt<8; nt++){
            float* p0 = C + (size_t)(row0 + mt*16)*Dn + col0 + nt*8;
            float* p1 = p0 + 8*(size_t)Dn;
            *(float2*)p0 = make_float2(acc[mt][nt][0], acc[mt][nt][1]);
            *(float2*)p1 = make_float2(acc[mt][nt][2], acc[mt][nt][3]);
        }
    }
}

// ======================= RoPE ===============================================
__global__ void build_rope_tables() {
    int idx = blockIdx.x * blockDim.x + threadIdx.x;
    if (idx >= MAXPOS*64) return;
    int pos = idx >> 6;
    int i   = idx & 63;
    float expo = (float)(2*i) * (1.0f/128.0f);
    float inv  = 1.0f / powf(10000.0f, expo);
    float ang  = (float)pos * inv;
    g_cos[idx] = cosf(ang);
    g_sin[idx] = sinf(ang);
}

__global__ void rope_apply(const int* __restrict__ tp) {
    int idx = blockIdx.x*blockDim.x + threadIdx.x;
    const int total = Bn*Ln*Hn*64;
    if (idx >= total) return;
    int i = idx & 63;
    int h = (idx >> 6) & (Hn-1);
    int l = (idx >> 10) & (Ln-1);
    int b = idx >> 21;
    int pos = tp[b*Ln + l];
    float c = g_cos[pos*64 + i];
    float s = g_sin[pos*64 + i];
    size_t off = ((size_t)(b*Ln + l))*Dn + h*128 + 2*i;
    float2 q = *(float2*)&g_Q[off];
    *(float2*)&g_Q[off] = make_float2(q.x*c - q.y*s, q.x*s + q.y*c);
    float2 k = *(float2*)&g_K[off];
    *(float2*)&g_K[off] = make_float2(k.x*c - k.y*s, k.x*s + k.y*c);
}

// ======================= causal flash attention, fp32 =======================
__global__ __launch_bounds__(256)
void attn_k(const float* __restrict__ Qg, const float* __restrict__ Kg,
            const float* __restrict__ Vg,
            __nv_bfloat16* __restrict__ Oh, __nv_bfloat16* __restrict__ Ol) {
    extern __shared__ float fsm[];
    float* sQ = fsm;                  // 64 x 132
    float* sK = sQ + 64*132;
    float* sV = sK + 64*132;
    float* sP = sV + 64*132;          // 64 x 68

    int tid = threadIdx.x;
    int tx = tid & 15, ty = tid >> 4;
    int qb = blockIdx.x;
    int bh = blockIdx.y;
    int b = bh >> 4, h = bh & 15;
    size_t rowbase = (size_t)b*Ln;
    size_t colbase = (size_t)h*128;

    for (int c = tid; c < 64*32; c += 256) {
        int r = c >> 5, c4 = (c & 31) << 2;
        *(float4*)&sQ[r*132 + c4] = *(const float4*)&Qg[(rowbase + qb*64 + r)*Dn + colbase + c4];
    }

    float o[4][8];
    #pragma unroll
    for (int r = 0; r < 4; r++)
        #pragma unroll
        for (int c = 0; c < 8; c++) o[r][c] = 0.f;
    float mrow[4] = {-1e30f,-1e30f,-1e30f,-1e30f};
    float lrow[4] = {0.f,0.f,0.f,0.f};
    const float scale = 0.08838834764831845f;

    for (int kb = 0; kb <= qb; kb++) {
        __syncthreads();
        for (int c = tid; c < 64*32; c += 256) {
            int r = c >> 5, c4 = (c & 31) << 2;
            size_t goff = (rowbase + kb*64 + r)*Dn + colbase + c4;
            *(float4*)&sK[r*132 + c4] = *(const float4*)&Kg[goff];
            *(float4*)&sV[r*132 + c4] = *(const float4*)&Vg[goff];
        }
        __syncthreads();

        float s[4][4];
        #pragma unroll
        for (int r = 0; r < 4; r++)
            #pragma unroll
            for (int j = 0; j < 4; j++) s[r][j] = 0.f;
        #pragma unroll 8
        for (int d = 0; d < 128; d += 4) {
            float4 q4[4], k4[4];
            #pragma unroll
            for (int r = 0; r < 4; r++) q4[r] = *(const float4*)&sQ[(ty*4+r)*132 + d];
            #pragma unroll
            for (int j = 0; j < 4; j++) k4[j] = *(const float4*)&sK[(tx*4+j)*132 + d];
            #pragma unroll
            for (int r = 0; r < 4; r++)
                #pragma unroll
                for (int j = 0; j < 4; j++)
                    s[r][j] += q4[r].x*k4[j].x + q4[r].y*k4[j].y
                             + q4[r].z*k4[j].z + q4[r].w*k4[j].w;
        }

        bool diag = (kb == qb);
        float rmax[4], fac[4], rsum[4];
        #pragma unroll
        for (int r = 0; r < 4; r++) {
            #pragma unroll
            for (int j = 0; j < 4; j++) {
                float v = s[r][j]*scale;
                if (diag && (tx*4+j) > (ty*4+r)) v = -1e30f;
                s[r][j] = v;
            }
            rmax[r] = fmaxf(fmaxf(s[r][0],s[r][1]), fmaxf(s[r][2],s[r][3]));
        }
        #pragma unroll
        for (int off = 8; off > 0; off >>= 1)
            #pragma unroll
            for (int r = 0; r < 4; r++)
                rmax[r] = fmaxf(rmax[r], __shfl_xor_sync(0xffffffffu, rmax[r], off));
        #pragma unroll
        for (int r = 0; r < 4; r++) {
            float mN = fmaxf(mrow[r], rmax[r]);
            fac[r] = __expf(mrow[r] - mN);
            mrow[r] = mN;
            float rs = 0.f;
            #pragma unroll
            for (int j = 0; j < 4; j++) {
                float p = __expf(s[r][j] - mN);
                s[r][j] = p;
                rs += p;
            }
            rsum[r] = rs;
        }
        #pragma unroll
        for (int off = 8; off > 0; off >>= 1)
            #pragma unroll
            for (int r = 0; r < 4; r++)
                rsum[r] += __shfl_xor_sync(0xffffffffu, rsum[r], off);
        #pragma unroll
        for (int r = 0; r < 4; r++) lrow[r] = lrow[r]*fac[r] + rsum[r];

        #pragma unroll
        for (int r = 0; r < 4; r++)
            #pragma unroll
            for (int j = 0; j < 4; j++)
                sP[(ty*4+r)*68 + tx*4+j] = s[r][j];
        __syncthreads();

        #pragma unroll
        for (int r = 0; r < 4; r++)
            #pragma unroll
            for (int c = 0; c < 8; c++) o[r][c] *= fac[r];
        #pragma unroll 4
        for (int j = 0; j < 64; j++) {
            float pv[4];
            #pragma unroll
            for (int r = 0; r < 4; r++) pv[r] = sP[(ty*4+r)*68 + j];
            float4 v0 = *(const float4*)&sV[j*132 + tx*8];
            float4 v1 = *(const float4*)&sV[j*132 + tx*8 + 4];
            #pragma unroll
            for (int r = 0; r < 4; r++) {
                o[r][0]+=pv[r]*v0.x; o[r][1]+=pv[r]*v0.y; o[r][2]+=pv[r]*v0.z; o[r][3]+=pv[r]*v0.w;
                o[r][4]+=pv[r]*v1.x; o[r][5]+=pv[r]*v1.y; o[r][6]+=pv[r]*v1.z; o[r][7]+=pv[r]*v1.w;
            }
        }
    }

    // epilogue: normalize + split to hi/lo bf16
    #pragma unroll
    for (int r = 0; r < 4; r++) {
        float inv = 1.0f / lrow[r];
        int l = qb*64 + ty*4 + r;
        size_t off = ((size_t)b*Ln + l)*Dn + h*128 + tx*8;
        float ov[8];
        #pragma unroll
        for (int c = 0; c < 8; c++) ov[c] = o[r][c]*inv;
        uint32_t hp[4], lp[4];
        #pragma unroll
        for (int q = 0; q < 4; q++){
            __nv_bfloat16 h0=__float2bfloat16(ov[2*q]), h1=__float2bfloat16(ov[2*q+1]);
            __nv_bfloat16 l0=__float2bfloat16(ov[2*q]  -__bfloat162float(h0));
            __nv_bfloat16 l1=__float2bfloat16(ov[2*q+1]-__bfloat162float(h1));
            hp[q] = pack2(h0,h1);
            lp[q] = pack2(l0,l1);
        }
        *(uint4*)&Oh[off] = make_uint4(hp[0],hp[1],hp[2],hp[3]);
        *(uint4*)&Ol[off] = make_uint4(lp[0],lp[1],lp[2],lp[3]);
    }
}

// ======================= launch =============================================
extern "C" void kernel_launch(void* const* d_in, const int* in_sizes, int n_in,
                              void* d_out, int out_size) {
    const float* x  = (const float*)d_in[0];
    const int*   tp = (const int*)d_in[2];
    const float* Wq = (const float*)d_in[3];
    const float* Wk = (const float*)d_in[4];
    const float* Wv = (const float*)d_in[5];
    const float* Wo = (const float*)d_in[6];
    float* out = (float*)d_out;

    float *Qp, *Kp, *Vp;
    __nv_bfloat16 *xh, *xl, *wh, *wl, *Ohp, *Olp;
    cudaGetSymbolAddress((void**)&Qp, g_Q);
    cudaGetSymbolAddress((void**)&Kp, g_K);
    cudaGetSymbolAddress((void**)&Vp, g_V);
    cudaGetSymbolAddress((void**)&xh, g_xh);
    cudaGetSymbolAddress((void**)&xl, g_xl);
    cudaGetSymbolAddress((void**)&wh, g_wh);
    cudaGetSymbolAddress((void**)&wl, g_wl);
    cudaGetSymbolAddress((void**)&Ohp, g_Oh);
    cudaGetSymbolAddress((void**)&Olp, g_Ol);
    const size_t WS = (size_t)Dn*Dn;

    cudaFuncSetAttribute((const void*)gemm_mma,
                         cudaFuncAttributeMaxDynamicSharedMemorySize, G_SMEM);
    const int smem_attn = (3*64*132 + 64*68) * (int)sizeof(float);
    cudaFuncSetAttribute((const void*)attn_k,
                         cudaFuncAttributeMaxDynamicSharedMemorySize, smem_attn);

    build_rope_tables<<<(MAXPOS*64 + 255)/256, 256>>>();

    // split x and the 4 weight matrices into hi/lo bf16
    const int n4x = MROWS*Dn/4, n4w = Dn*Dn/4;
    split_prep<<<(n4x+255)/256, 256>>>(x,  xh,        xl,        n4x);
    split_prep<<<(n4w+255)/256, 256>>>(Wq, wh+0*WS,   wl+0*WS,   n4w);
    split_prep<<<(n4w+255)/256, 256>>>(Wk, wh+1*WS,   wl+1*WS,   n4w);
    split_prep<<<(n4w+255)/256, 256>>>(Wv, wh+2*WS,   wl+2*WS,   n4w);
    split_prep<<<(n4w+255)/256, 256>>>(Wo, wh+3*WS,   wl+3*WS,   n4w);

    // fused QKV projections
    gemm_mma<<<dim3(Dn/256, MROWS/128, 3), 256, G_SMEM>>>(
        xh, xl,
        wh+0*WS, wl+0*WS, wh+1*WS, wl+1*WS, wh+2*WS, wl+2*WS,
        Qp, Kp, Vp);

    rope_apply<<<(Bn*Ln*Hn*64 + 255)/256, 256>>>(tp);

    attn_k<<<dim3(Ln/64, Bn*Hn), 256, smem_attn>>>(Qp, Kp, Vp, Ohp, Olp);

    // output projection
    gemm_mma<<<dim3(Dn/256, MROWS/128, 1), 256, G_SMEM>>>(
        Ohp, Olp,
        wh+3*WS, wl+3*WS, wh+3*WS, wl+3*WS, wh+3*WS, wl+3*WS,
        out, out, out);
}

// round 4
// speedup vs baseline: 2.9454x; 1.9041x over previous
#include <cuda_runtime.h>
#include <cuda_bf16.h>
#include <math.h>
#include <stdint.h>

#define Bn 2
#define Ln 2048
#define Dn 2048
#define Hn 16
#define DHn 128
#define MROWS (Bn*Ln)          // 4096
#define MAXPOS 4096

// ---------------- scratch (device globals; no allocation allowed) ----------
__device__ float g_Q[(size_t)MROWS*Dn];
__device__ float g_K[(size_t)MROWS*Dn];
__device__ float g_V[(size_t)MROWS*Dn];
__device__ __nv_bfloat16 g_xh[(size_t)MROWS*Dn];
__device__ __nv_bfloat16 g_xl[(size_t)MROWS*Dn];
__device__ __nv_bfloat16 g_wh[4][(size_t)Dn*Dn];
__device__ __nv_bfloat16 g_wl[4][(size_t)Dn*Dn];
__device__ __nv_bfloat16 g_Qh[(size_t)MROWS*Dn];
__device__ __nv_bfloat16 g_Ql[(size_t)MROWS*Dn];
__device__ __nv_bfloat16 g_Kh[(size_t)MROWS*Dn];
__device__ __nv_bfloat16 g_Kl[(size_t)MROWS*Dn];
__device__ __nv_bfloat16 g_Vh[(size_t)MROWS*Dn];
__device__ __nv_bfloat16 g_Vl[(size_t)MROWS*Dn];
__device__ __nv_bfloat16 g_Oh[(size_t)MROWS*Dn];
__device__ __nv_bfloat16 g_Ol[(size_t)MROWS*Dn];
__device__ float g_cos[MAXPOS*64];
__device__ float g_sin[MAXPOS*64];

// ======================= helpers ============================================
__device__ __forceinline__ uint32_t smem_u32(const void* p){
    uint32_t a;
    asm("{ .reg .u64 t; cvta.to.shared.u64 t, %1; cvt.u32.u64 %0, t; }" : "=r"(a) : "l"(p));
    return a;
}
__device__ __forceinline__ void cp16(uint32_t s, const void* g){
    asm volatile("cp.async.cg.shared.global [%0], [%1], 16;" :: "r"(s), "l"(g));
}
__device__ __forceinline__ void ldsm4(uint32_t* r, uint32_t a){
    asm volatile("ldmatrix.sync.aligned.m8n8.x4.shared.b16 {%0,%1,%2,%3},[%4];"
        : "=r"(r[0]),"=r"(r[1]),"=r"(r[2]),"=r"(r[3]) : "r"(a));
}
__device__ __forceinline__ void ldsm4t(uint32_t* r, uint32_t a){
    asm volatile("ldmatrix.sync.aligned.m8n8.x4.trans.shared.b16 {%0,%1,%2,%3},[%4];"
        : "=r"(r[0]),"=r"(r[1]),"=r"(r[2]),"=r"(r[3]) : "r"(a));
}
__device__ __forceinline__ void mma16816(float* c, const uint32_t* a, uint32_t b0, uint32_t b1){
    asm volatile("mma.sync.aligned.m16n8k16.row.col.f32.bf16.bf16.f32 "
        "{%0,%1,%2,%3},{%4,%5,%6,%7},{%8,%9},{%0,%1,%2,%3};"
        : "+f"(c[0]),"+f"(c[1]),"+f"(c[2]),"+f"(c[3])
        : "r"(a[0]),"r"(a[1]),"r"(a[2]),"r"(a[3]),"r"(b0),"r"(b1));
}
__device__ __forceinline__ uint32_t pack2(__nv_bfloat16 a, __nv_bfloat16 b){
    return ((uint32_t)__bfloat16_as_ushort(b)<<16) | (uint32_t)__bfloat16_as_ushort(a);
}
__device__ __forceinline__ void splitpack(float x, float y, uint32_t& hp, uint32_t& lp){
    __nv_bfloat16 hx=__float2bfloat16(x), hy=__float2bfloat16(y);
    __nv_bfloat16 lx=__float2bfloat16(x-__bfloat162float(hx));
    __nv_bfloat16 ly=__float2bfloat16(y-__bfloat162float(hy));
    hp = pack2(hx,hy); lp = pack2(lx,ly);
}

// ======================= split prep: f32 -> hi/lo bf16 ======================
__global__ void split_prep(const float* __restrict__ src,
                           __nv_bfloat16* __restrict__ h, __nv_bfloat16* __restrict__ l, int n4){
    int i = blockIdx.x*blockDim.x + threadIdx.x;
    if (i >= n4) return;
    float4 v = ((const float4*)src)[i];
    uint32_t h0,h1,l0,l1;
    splitpack(v.x, v.y, h0, l0);
    splitpack(v.z, v.w, h1, l1);
    ((uint2*)h)[i] = make_uint2(h0,h1);
    ((uint2*)l)[i] = make_uint2(l0,l1);
}

// ======================= split-bf16 mma.sync GEMM ===========================
#define SA_L_OFF 10240
#define SW_H_OFF 20480
#define SW_L_OFF 40960
#define STAGE_B  61440
#define G_SMEM   (3*STAGE_B)   // 184320

__global__ __launch_bounds__(256)
void gemm_mma(const __nv_bfloat16* __restrict__ Ah, const __nv_bfloat16* __restrict__ Al,
              const __nv_bfloat16* __restrict__ W0h, const __nv_bfloat16* __restrict__ W0l,
              const __nv_bfloat16* __restrict__ W1h, const __nv_bfloat16* __restrict__ W1l,
              const __nv_bfloat16* __restrict__ W2h, const __nv_bfloat16* __restrict__ W2l,
              float* __restrict__ C0, float* __restrict__ C1, float* __restrict__ C2)
{
    extern __shared__ char smem[];
    uint32_t sb = smem_u32(smem);
    const int tid = threadIdx.x, wid = tid>>5, lane = tid&31;
    const int z = blockIdx.z;
    const __nv_bfloat16* Wh = (z==0)?W0h:((z==1)?W1h:W2h);
    const __nv_bfloat16* Wl = (z==0)?W0l:((z==1)?W1l:W2l);
    float* C = (z==0)?C0:((z==1)?C1:C2);
    const int m0 = blockIdx.y*128, n0 = blockIdx.x*256;
    const int warp_m = (wid>>2)*64, warp_n = (wid&3)*64;

    auto load_stage = [&](int st, int kt){
        uint32_t sbase = sb + st*STAGE_B;
        #pragma unroll
        for (int j=0;j<12;j++){
            int c = tid + j*256;
            uint32_t dst; const char* src;
            if (c < 1024){
                int cc = c & 511; int row = cc>>2, seg = cc&3;
                const char* base = (c<512)? (const char*)Ah : (const char*)Al;
                src = base + (((size_t)(m0+row)*Dn + kt*32)<<1) + seg*16;
                dst = sbase + ((c<512)?0u:(uint32_t)SA_L_OFF) + row*80 + seg*16;
            } else {
                int cc = (c-1024) & 1023; int row = cc>>2, seg = cc&3;
                const char* base = (c<2048)? (const char*)Wh : (const char*)Wl;
                src = base + (((size_t)(n0+row)*Dn + kt*32)<<1) + seg*16;
                dst = sbase + ((c<2048)?(uint32_t)SW_H_OFF:(uint32_t)SW_L_OFF) + row*80 + seg*16;
            }
            cp16(dst, src);
        }
    };

    float acc[4][8][4];
    #pragma unroll
    for (int i=0;i<4;i++)
        #pragma unroll
        for (int j=0;j<8;j++)
            #pragma unroll
            for (int q=0;q<4;q++) acc[i][j][q]=0.f;

    load_stage(0, 0);
    asm volatile("cp.async.commit_group;");
    load_stage(1, 1);
    asm volatile("cp.async.commit_group;");

    const int lrow = lane & 15;
    const uint32_t lcolB = (uint32_t)((lane>>4)<<4);

    for (int kt=0; kt<64; ++kt){
        int st = kt - (kt/3)*3;
        uint32_t base = sb + st*STAGE_B;
        asm volatile("cp.async.wait_group 1;");
        __syncthreads();

        #pragma unroll
        for (int ks=0; ks<2; ++ks){
            uint32_t kB = ks*32;
            uint32_t aAddr = base + (uint32_t)(warp_m + lrow)*80 + lcolB + kB;
            uint32_t wAddr = base + SW_H_OFF + (uint32_t)(warp_n + lrow)*80 + lcolB + kB;

            uint32_t ahr[4][4], whr[4][4];
            #pragma unroll
            for (int mt=0; mt<4; mt++) ldsm4(ahr[mt], aAddr + mt*(16*80));
            #pragma unroll
            for (int p=0; p<4; p++)   ldsm4(whr[p], wAddr + p*(16*80));
            #pragma unroll
            for (int mt=0; mt<4; mt++)
                #pragma unroll
                for (int p=0; p<4; p++){
                    mma16816(acc[mt][2*p],   ahr[mt], whr[p][0], whr[p][2]);
                    mma16816(acc[mt][2*p+1], ahr[mt], whr[p][1], whr[p][3]);
                }
            {
                uint32_t wlr[4][4];
                #pragma unroll
                for (int p=0; p<4; p++) ldsm4(wlr[p], wAddr + (SW_L_OFF-SW_H_OFF) + p*(16*80));
                #pragma unroll
                for (int mt=0; mt<4; mt++)
                    #pragma unroll
                    for (int p=0; p<4; p++){
                        mma16816(acc[mt][2*p],   ahr[mt], wlr[p][0], wlr[p][2]);
                        mma16816(acc[mt][2*p+1], ahr[mt], wlr[p][1], wlr[p][3]);
                    }
            }
            {
                uint32_t alr[4][4];
                #pragma unroll
                for (int mt=0; mt<4; mt++) ldsm4(alr[mt], aAddr + SA_L_OFF + mt*(16*80));
                #pragma unroll
                for (int mt=0; mt<4; mt++)
                    #pragma unroll
                    for (int p=0; p<4; p++){
                        mma16816(acc[mt][2*p],   alr[mt], whr[p][0], whr[p][2]);
                        mma16816(acc[mt][2*p+1], alr[mt], whr[p][1], whr[p][3]);
                    }
            }
        }

        if (kt+2 < 64){
            int st2 = (kt+2) - ((kt+2)/3)*3;
            load_stage(st2, kt+2);
        }
        asm volatile("cp.async.commit_group;");
        __syncthreads();
    }

    const int row0 = m0 + warp_m + (lane>>2);
    const int col0 = n0 + warp_n + ((lane&3)<<1);
    #pragma unroll
    for (int mt=0; mt<4; mt++){
        #pragma unroll
        for (int nt=0; nt<8; nt++){
            float* p0 = C + (size_t)(row0 + mt*16)*Dn + col0 + nt*8;
            float* p1 = p0 + 8*(size_t)Dn;
            *(float2*)p0 = make_float2(acc[mt][nt][0], acc[mt][nt][1]);
            *(float2*)p1 = make_float2(acc[mt][nt][2], acc[mt][nt][3]);
        }
    }
}

// ======================= RoPE ===============================================
__global__ void build_rope_tables() {
    int idx = blockIdx.x * blockDim.x + threadIdx.x;
    if (idx >= MAXPOS*64) return;
    int pos = idx >> 6;
    int i   = idx & 63;
    float expo = (float)(2*i) * (1.0f/128.0f);
    float inv  = 1.0f / powf(10000.0f, expo);
    float ang  = (float)pos * inv;
    g_cos[idx] = cosf(ang);
    g_sin[idx] = sinf(ang);
}

__global__ void rope_apply(const int* __restrict__ tp) {
    int idx = blockIdx.x*blockDim.x + threadIdx.x;
    const int total = Bn*Ln*Hn*64;
    if (idx >= total) return;
    int i = idx & 63;
    int h = (idx >> 6) & (Hn-1);
    int l = (idx >> 10) & (Ln-1);
    int b = idx >> 21;
    int pos = tp[b*Ln + l];
    float c = g_cos[pos*64 + i];
    float s = g_sin[pos*64 + i];
    size_t off = ((size_t)(b*Ln + l))*Dn + h*128 + 2*i;
    float2 q = *(float2*)&g_Q[off];
    *(float2*)&g_Q[off] = make_float2(q.x*c - q.y*s, q.x*s + q.y*c);
    float2 k = *(float2*)&g_K[off];
    *(float2*)&g_K[off] = make_float2(k.x*c - k.y*s, k.x*s + k.y*c);
}

// ======================= tensor-core flash attention ========================
// CTA: 128 q-rows x one head. 8 warps: warp w owns q rows w*16..w*16+15.
// K/V tiles: 64 rows, hi/lo bf16, 2-stage cp.async pipeline.
// S = Q K^T and O += P V, both 3-term split-bf16 mma.sync. Softmax fp32.
#define AT_ROWB 272                          // padded row: 136 bf16 = 272 B
#define AT_KH   0
#define AT_KL   17408
#define AT_VH   34816
#define AT_VL   52224
#define AT_STAGE 69632
#define AT_QOFF (2*AT_STAGE)                 // Q staging: hi then lo
#define AT_SMEM (2*AT_STAGE + 69632)         // 208896

__global__ __launch_bounds__(256, 1)
void attn_mma(const __nv_bfloat16* __restrict__ Qh, const __nv_bfloat16* __restrict__ Ql,
              const __nv_bfloat16* __restrict__ Kh_, const __nv_bfloat16* __restrict__ Kl_,
              const __nv_bfloat16* __restrict__ Vh_, const __nv_bfloat16* __restrict__ Vl_,
              __nv_bfloat16* __restrict__ Oh, __nv_bfloat16* __restrict__ Ol)
{
    extern __shared__ char sm[];
    uint32_t sb = smem_u32(sm);
    const int tid = threadIdx.x, w = tid>>5, lane = tid&31;
    const int qb = (int)(gridDim.x - 1 - blockIdx.x);     // heavy tiles first
    const int bh = blockIdx.y;
    const int b = bh>>4, h = bh&15;
    const size_t rowbase = (size_t)b*Ln;
    const size_t colb = (size_t)h*128;
    const int kmax = 2*qb + 1;

    // ---- prologue: cp.async Q (group 0), KV tile 0 (group 1) ----
    {   // Q: 4096 16B chunks (hi 2048, lo 2048)
        #pragma unroll
        for (int j=0;j<16;j++){
            int c = tid + j*256;
            int half = c>>11, r = (c>>4)&127, seg = c&15;
            const char* src = (const char*)(half?Ql:Qh)
                + (((rowbase + (size_t)qb*128 + r)*Dn + colb)<<1) + seg*16;
            cp16(sb + AT_QOFF + half*34816 + r*AT_ROWB + seg*16, src);
        }
        asm volatile("cp.async.commit_group;");
    }
    auto issue_kv = [&](int kb2, int st){
        uint32_t sbase = sb + st*AT_STAGE;
        #pragma unroll
        for (int j=0;j<16;j++){
            int c = tid + j*256;
            int arr = c>>10, r = (c>>4)&63, seg = c&15;
            const char* base = (arr==0)?(const char*)Kh_:((arr==1)?(const char*)Kl_:
                               ((arr==2)?(const char*)Vh_:(const char*)Vl_));
            const char* src = base + (((rowbase + (size_t)kb2*64 + r)*Dn + colb)<<1) + seg*16;
            cp16(sbase + arr*17408 + r*AT_ROWB + seg*16, src);
        }
    };
    issue_kv(0, 0);
    asm volatile("cp.async.commit_group;");

    // ---- Q fragments to registers (persistent) ----
    asm volatile("cp.async.wait_group 1;");
    __syncthreads();
    uint32_t qh[8][4], ql[8][4];
    {
        uint32_t qa = sb + AT_QOFF + (uint32_t)(w*16 + (lane&15))*AT_ROWB + ((lane>>4)<<4);
        #pragma unroll
        for (int ks=0; ks<8; ks++){
            ldsm4(qh[ks], qa + ks*32);
            ldsm4(ql[ks], qa + ks*32 + 34816);
        }
    }

    float o[16][4];
    #pragma unroll
    for (int i=0;i<16;i++){ o[i][0]=0.f;o[i][1]=0.f;o[i][2]=0.f;o[i][3]=0.f; }
    float m0 = -1e30f, m1 = -1e30f, l0 = 0.f, l1 = 0.f;
    const float scale = 0.08838834764831845f;
    const int grow0 = qb*128 + w*16 + (lane>>2);

    for (int kb=0; kb<=kmax; ++kb){
        __syncthreads();                       // all warps done with other stage
        if (kb+1 <= kmax) issue_kv(kb+1, (kb+1)&1);
        asm volatile("cp.async.commit_group;");
        asm volatile("cp.async.wait_group 1;");
        __syncthreads();
        uint32_t base = sb + (uint32_t)(kb&1)*AT_STAGE;

        // ---- S = Q K^T (3-term) ----
        float s[8][4];
        #pragma unroll
        for (int j=0;j<8;j++){ s[j][0]=0.f;s[j][1]=0.f;s[j][2]=0.f;s[j][3]=0.f; }
        uint32_t kaBase = base + (uint32_t)(lane&15)*AT_ROWB + ((lane>>4)<<4);
        #pragma unroll
        for (int ks=0; ks<8; ks++){
            #pragma unroll
            for (int p2=0; p2<4; p2++){
                uint32_t ka = kaBase + (uint32_t)p2*(16*AT_ROWB) + ks*32;
                uint32_t bh4[4], bl4[4];
                ldsm4(bh4, ka + AT_KH);
                ldsm4(bl4, ka + AT_KL);
                mma16816(s[2*p2],   qh[ks], bh4[0], bh4[2]);
                mma16816(s[2*p2+1], qh[ks], bh4[1], bh4[3]);
                mma16816(s[2*p2],   qh[ks], bl4[0], bl4[2]);
                mma16816(s[2*p2+1], qh[ks], bl4[1], bl4[3]);
                mma16816(s[2*p2],   ql[ks], bh4[0], bh4[2]);
                mma16816(s[2*p2+1], ql[ks], bh4[1], bh4[3]);
            }
        }

        // ---- scale + causal mask ----
        if (kb >= 2*qb){
            #pragma unroll
            for (int j=0;j<8;j++){
                int gc = kb*64 + j*8 + ((lane&3)<<1);
                s[j][0] = (gc   <= grow0)   ? s[j][0]*scale : -1e30f;
                s[j][1] = (gc+1 <= grow0)   ? s[j][1]*scale : -1e30f;
                s[j][2] = (gc   <= grow0+8) ? s[j][2]*scale : -1e30f;
                s[j][3] = (gc+1 <= grow0+8) ? s[j][3]*scale : -1e30f;
            }
        } else {
            #pragma unroll
            for (int j=0;j<8;j++){
                s[j][0]*=scale; s[j][1]*=scale; s[j][2]*=scale; s[j][3]*=scale;
            }
        }

        // ---- online softmax (rows r0 = lane>>2, r1 = r0+8) ----
        float rm0 = -1e30f, rm1 = -1e30f;
        #pragma unroll
        for (int j=0;j<8;j++){
            rm0 = fmaxf(rm0, fmaxf(s[j][0], s[j][1]));
            rm1 = fmaxf(rm1, fmaxf(s[j][2], s[j][3]));
        }
        rm0 = fmaxf(rm0, __shfl_xor_sync(0xffffffffu, rm0, 1));
        rm0 = fmaxf(rm0, __shfl_xor_sync(0xffffffffu, rm0, 2));
        rm1 = fmaxf(rm1, __shfl_xor_sync(0xffffffffu, rm1, 1));
        rm1 = fmaxf(rm1, __shfl_xor_sync(0xffffffffu, rm1, 2));
        float mN0 = fmaxf(m0, rm0), mN1 = fmaxf(m1, rm1);
        float fac0 = __expf(m0 - mN0), fac1 = __expf(m1 - mN1);
        m0 = mN0; m1 = mN1;
        float rs0 = 0.f, rs1 = 0.f;
        #pragma unroll
        for (int j=0;j<8;j++){
            s[j][0] = __expf(s[j][0] - mN0);
            s[j][1] = __expf(s[j][1] - mN0);
            s[j][2] = __expf(s[j][2] - mN1);
            s[j][3] = __expf(s[j][3] - mN1);
            rs0 += s[j][0] + s[j][1];
            rs1 += s[j][2] + s[j][3];
        }
        rs0 += __shfl_xor_sync(0xffffffffu, rs0, 1);
        rs0 += __shfl_xor_sync(0xffffffffu, rs0, 2);
        rs1 += __shfl_xor_sync(0xffffffffu, rs1, 1);
        rs1 += __shfl_xor_sync(0xffffffffu, rs1, 2);
        l0 = l0*fac0 + rs0;
        l1 = l1*fac1 + rs1;
        #pragma unroll
        for (int i=0;i<16;i++){
            o[i][0]*=fac0; o[i][1]*=fac0; o[i][2]*=fac1; o[i][3]*=fac1;
        }

        // ---- O += P V (3-term) ----
        uint32_t vaBase = base + ((uint32_t)(lane&7) + (((lane>>3)&1)<<3))*AT_ROWB
                               + (((lane>>4)<<3)<<1);
        #pragma unroll
        for (int ks=0; ks<4; ks++){
            uint32_t aH[4], aL[4];
            splitpack(s[2*ks][0],   s[2*ks][1],   aH[0], aL[0]);
            splitpack(s[2*ks][2],   s[2*ks][3],   aH[1], aL[1]);
            splitpack(s[2*ks+1][0], s[2*ks+1][1], aH[2], aL[2]);
            splitpack(s[2*ks+1][2], s[2*ks+1][3], aH[3], aL[3]);
            #pragma unroll
            for (int nt2=0; nt2<8; nt2++){
                uint32_t va = vaBase + (uint32_t)ks*(16*AT_ROWB) + (uint32_t)nt2*32;
                uint32_t vh4[4], vl4[4];
                ldsm4t(vh4, va + AT_VH);
                ldsm4t(vl4, va + AT_VL);
                mma16816(o[2*nt2],   aH, vh4[0], vh4[1]);
                mma16816(o[2*nt2+1], aH, vh4[2], vh4[3]);
                mma16816(o[2*nt2],   aH, vl4[0], vl4[1]);
                mma16816(o[2*nt2+1], aH, vl4[2], vl4[3]);
                mma16816(o[2*nt2],   aL, vh4[0], vh4[1]);
                mma16816(o[2*nt2+1], aL, vh4[2], vh4[3]);
            }
        }
    }

    // ---- epilogue: normalize + split-store to Oh/Ol ----
    float inv0 = 1.0f/l0, inv1 = 1.0f/l1;
    size_t r0off = (rowbase + (size_t)grow0)*Dn + colb + ((lane&3)<<1);
    size_t r1off = r0off + 8*(size_t)Dn;
    #pragma unroll
    for (int nt=0; nt<16; nt++){
        uint32_t hp, lp;
        splitpack(o[nt][0]*inv0, o[nt][1]*inv0, hp, lp);
        *(uint32_t*)&Oh[r0off + nt*8] = hp;
        *(uint32_t*)&Ol[r0off + nt*8] = lp;
        splitpack(o[nt][2]*inv1, o[nt][3]*inv1, hp, lp);
        *(uint32_t*)&Oh[r1off + nt*8] = hp;
        *(uint32_t*)&Ol[r1off + nt*8] = lp;
    }
}

// ======================= launch =============================================
extern "C" void kernel_launch(void* const* d_in, const int* in_sizes, int n_in,
                              void* d_out, int out_size) {
    const float* x  = (const float*)d_in[0];
    const int*   tp = (const int*)d_in[2];
    const float* Wq = (const float*)d_in[3];
    const float* Wk = (const float*)d_in[4];
    const float* Wv = (const float*)d_in[5];
    const float* Wo = (const float*)d_in[6];
    float* out = (float*)d_out;

    float *Qp, *Kp, *Vp;
    __nv_bfloat16 *xh, *xl, *wh, *wl, *Ohp, *Olp;
    __nv_bfloat16 *Qhp,*Qlp,*Khp,*Klp,*Vhp,*Vlp;
    cudaGetSymbolAddress((void**)&Qp, g_Q);
    cudaGetSymbolAddress((void**)&Kp, g_K);
    cudaGetSymbolAddress((void**)&Vp, g_V);
    cudaGetSymbolAddress((void**)&xh, g_xh);
    cudaGetSymbolAddress((void**)&xl, g_xl);
    cudaGetSymbolAddress((void**)&wh, g_wh);
    cudaGetSymbolAddress((void**)&wl, g_wl);
    cudaGetSymbolAddress((void**)&Ohp, g_Oh);
    cudaGetSymbolAddress((void**)&Olp, g_Ol);
    cudaGetSymbolAddress((void**)&Qhp, g_Qh);
    cudaGetSymbolAddress((void**)&Qlp, g_Ql);
    cudaGetSymbolAddress((void**)&Khp, g_Kh);
    cudaGetSymbolAddress((void**)&Klp, g_Kl);
    cudaGetSymbolAddress((void**)&Vhp, g_Vh);
    cudaGetSymbolAddress((void**)&Vlp, g_Vl);
    const size_t WS = (size_t)Dn*Dn;

    cudaFuncSetAttribute((const void*)gemm_mma,
                         cudaFuncAttributeMaxDynamicSharedMemorySize, G_SMEM);
    cudaFuncSetAttribute((const void*)attn_mma,
                         cudaFuncAttributeMaxDynamicSharedMemorySize, AT_SMEM);

    build_rope_tables<<<(MAXPOS*64 + 255)/256, 256>>>();

    const int n4x = MROWS*Dn/4, n4w = Dn*Dn/4;
    split_prep<<<(n4x+255)/256, 256>>>(x,  xh,      xl,      n4x);
    split_prep<<<(n4w+255)/256, 256>>>(Wq, wh+0*WS, wl+0*WS, n4w);
    split_prep<<<(n4w+255)/256, 256>>>(Wk, wh+1*WS, wl+1*WS, n4w);
    split_prep<<<(n4w+255)/256, 256>>>(Wv, wh+2*WS, wl+2*WS, n4w);
    split_prep<<<(n4w+255)/256, 256>>>(Wo, wh+3*WS, wl+3*WS, n4w);

    // QKV projections (fp32 out)
    gemm_mma<<<dim3(Dn/256, MROWS/128, 3), 256, G_SMEM>>>(
        xh, xl,
        wh+0*WS, wl+0*WS, wh+1*WS, wl+1*WS, wh+2*WS, wl+2*WS,
        Qp, Kp, Vp);

    rope_apply<<<(Bn*Ln*Hn*64 + 255)/256, 256>>>(tp);

    // split Q,K,V to hi/lo bf16 for the attention kernel
    split_prep<<<(n4x+255)/256, 256>>>(Qp, Qhp, Qlp, n4x);
    split_prep<<<(n4x+255)/256, 256>>>(Kp, Khp, Klp, n4x);
    split_prep<<<(n4x+255)/256, 256>>>(Vp, Vhp, Vlp, n4x);

    attn_mma<<<dim3(Ln/128, Bn*Hn), 256, AT_SMEM>>>(
        Qhp, Qlp, Khp, Klp, Vhp, Vlp, Ohp, Olp);

    // output projection
    gemm_mma<<<dim3(Dn/256, MROWS/128, 1), 256, G_SMEM>>>(
        Ohp, Olp,
        wh+3*WS, wl+3*WS, wh+3*WS, wl+3*WS, wh+3*WS, wl+3*WS,
        out, out, out);
}

// round 5
// speedup vs baseline: 4.0044x; 1.3596x over previous
#include <cuda_runtime.h>
#include <cuda_bf16.h>
#include <math.h>
#include <stdint.h>

#define Bn 2
#define Ln 2048
#define Dn 2048
#define Hn 16
#define DHn 128
#define MROWS (Bn*Ln)          // 4096
#define MAXPOS 4096

// ---------------- scratch (device globals; no allocation allowed) ----------
__device__ float g_Q[(size_t)MROWS*Dn];
__device__ float g_K[(size_t)MROWS*Dn];
__device__ float g_V[(size_t)MROWS*Dn];
__device__ float g_O[(size_t)MROWS*Dn];
__device__ __nv_bfloat16 g_Qh[(size_t)MROWS*Dn];
__device__ __nv_bfloat16 g_Ql[(size_t)MROWS*Dn];
__device__ __nv_bfloat16 g_Kh[(size_t)MROWS*Dn];
__device__ __nv_bfloat16 g_Kl[(size_t)MROWS*Dn];
__device__ __nv_bfloat16 g_Vh[(size_t)MROWS*Dn];
__device__ __nv_bfloat16 g_Vl[(size_t)MROWS*Dn];
__device__ float g_cos[MAXPOS*64];
__device__ float g_sin[MAXPOS*64];

// ======================= helpers ============================================
__device__ __forceinline__ uint32_t smem_u32(const void* p){
    uint32_t a;
    asm("{ .reg .u64 t; cvta.to.shared.u64 t, %1; cvt.u32.u64 %0, t; }" : "=r"(a) : "l"(p));
    return a;
}
__device__ __forceinline__ void cp16(uint32_t s, const void* g){
    asm volatile("cp.async.cg.shared.global [%0], [%1], 16;" :: "r"(s), "l"(g));
}
__device__ __forceinline__ void ldsm4(uint32_t* r, uint32_t a){
    asm volatile("ldmatrix.sync.aligned.m8n8.x4.shared.b16 {%0,%1,%2,%3},[%4];"
        : "=r"(r[0]),"=r"(r[1]),"=r"(r[2]),"=r"(r[3]) : "r"(a));
}
__device__ __forceinline__ void ldsm4t(uint32_t* r, uint32_t a){
    asm volatile("ldmatrix.sync.aligned.m8n8.x4.trans.shared.b16 {%0,%1,%2,%3},[%4];"
        : "=r"(r[0]),"=r"(r[1]),"=r"(r[2]),"=r"(r[3]) : "r"(a));
}
__device__ __forceinline__ void mma16816(float* c, const uint32_t* a, uint32_t b0, uint32_t b1){
    asm volatile("mma.sync.aligned.m16n8k16.row.col.f32.bf16.bf16.f32 "
        "{%0,%1,%2,%3},{%4,%5,%6,%7},{%8,%9},{%0,%1,%2,%3};"
        : "+f"(c[0]),"+f"(c[1]),"+f"(c[2]),"+f"(c[3])
        : "r"(a[0]),"r"(a[1]),"r"(a[2]),"r"(a[3]),"r"(b0),"r"(b1));
}
__device__ __forceinline__ void mma_tf32(float* c, const uint32_t* a, uint32_t b0, uint32_t b1){
    asm volatile("mma.sync.aligned.m16n8k8.row.col.f32.tf32.tf32.f32 "
        "{%0,%1,%2,%3},{%4,%5,%6,%7},{%8,%9},{%0,%1,%2,%3};"
        : "+f"(c[0]),"+f"(c[1]),"+f"(c[2]),"+f"(c[3])
        : "r"(a[0]),"r"(a[1]),"r"(a[2]),"r"(a[3]),"r"(b0),"r"(b1));
}
__device__ __forceinline__ uint32_t f2tf32(float f){
    uint32_t r;
    asm("cvt.rna.tf32.f32 %0, %1;" : "=r"(r) : "f"(f));
    return r;
}
__device__ __forceinline__ uint32_t pack2(__nv_bfloat16 a, __nv_bfloat16 b){
    return ((uint32_t)__bfloat16_as_ushort(b)<<16) | (uint32_t)__bfloat16_as_ushort(a);
}
__device__ __forceinline__ void splitpack(float x, float y, uint32_t& hp, uint32_t& lp){
    __nv_bfloat16 hx=__float2bfloat16(x), hy=__float2bfloat16(y);
    __nv_bfloat16 lx=__float2bfloat16(x-__bfloat162float(hx));
    __nv_bfloat16 ly=__float2bfloat16(y-__bfloat162float(hy));
    hp = pack2(hx,hy); lp = pack2(lx,ly);
}

// ======================= TF32 mma.sync GEMM =================================
// C[m,n] = sum_k A[m,k]*W[n,k], K=2048, fp32 in/out, tf32 compute (RNA).
// CTA 128x256, BK=32, 8 warps (2x4), warp tile 64x64, 3-stage cp.async.
// smem per stage: A[128][36]f32 (18432B) + W[256][36]f32 (36864B) = 55296B.
#define TSA     18432
#define TSTAGE  55296
#define TG_SMEM (3*TSTAGE)   // 165888

__global__ __launch_bounds__(256)
void gemm_tf32(const float* __restrict__ A,
               const float* __restrict__ W0, const float* __restrict__ W1, const float* __restrict__ W2,
               float* __restrict__ C0, float* __restrict__ C1, float* __restrict__ C2)
{
    extern __shared__ char smem[];
    uint32_t sb = smem_u32(smem);
    const int tid = threadIdx.x, wid = tid>>5, lane = tid&31;
    const int z = blockIdx.z;
    const float* W = (z==0)?W0:((z==1)?W1:W2);
    float*       C = (z==0)?C0:((z==1)?C1:C2);
    const int m0 = blockIdx.y*128, n0 = blockIdx.x*256;
    const int warp_m = (wid>>2)*64, warp_n = (wid&3)*64;

    auto load_stage = [&](int st, int kt){
        uint32_t sbase = sb + st*TSTAGE;
        #pragma unroll
        for (int j=0;j<12;j++){
            int c = tid + j*256;
            if (c < 1024){
                int row = c>>3, seg = c&7;
                cp16(sbase + row*144 + seg*16,
                     A + (size_t)(m0+row)*Dn + kt*32 + seg*4);
            } else {
                int cc = c - 1024; int row = cc>>3, seg = cc&7;
                cp16(sbase + TSA + row*144 + seg*16,
                     W + (size_t)(n0+row)*Dn + kt*32 + seg*4);
            }
        }
    };

    float acc[4][8][4];
    #pragma unroll
    for (int i=0;i<4;i++)
        #pragma unroll
        for (int j=0;j<8;j++)
            #pragma unroll
            for (int q=0;q<4;q++) acc[i][j][q]=0.f;

    load_stage(0, 0);
    asm volatile("cp.async.commit_group;");
    load_stage(1, 1);
    asm volatile("cp.async.commit_group;");

    const char* smc = smem;
    const uint32_t g = (uint32_t)(lane>>2);   // group 0..7
    const uint32_t cq = (uint32_t)(lane&3);   // 0..3

    for (int kt=0; kt<64; ++kt){
        int st = kt - (kt/3)*3;
        uint32_t boff = (uint32_t)st*TSTAGE;
        asm volatile("cp.async.wait_group 1;");
        __syncthreads();

        #pragma unroll
        for (int ks=0; ks<4; ks++){
            uint32_t colB = (cq + (uint32_t)ks*8)*4;
            // B fragments: W rows n = warp_n + nt*8 + g, cols k and k+4
            uint32_t bf[8][2];
            uint32_t bbase = boff + TSA + (uint32_t)(warp_n + g)*144 + colB;
            #pragma unroll
            for (int nt=0; nt<8; nt++){
                bf[nt][0] = f2tf32(*(const float*)(smc + bbase + nt*(8*144)));
                bf[nt][1] = f2tf32(*(const float*)(smc + bbase + nt*(8*144) + 16));
            }
            uint32_t abase = boff + (uint32_t)(warp_m + g)*144 + colB;
            #pragma unroll
            for (int mt=0; mt<4; mt++){
                uint32_t af[4];
                const char* ap = smc + abase + mt*(16*144);
                af[0] = f2tf32(*(const float*)(ap));
                af[1] = f2tf32(*(const float*)(ap + 8*144));
                af[2] = f2tf32(*(const float*)(ap + 16));
                af[3] = f2tf32(*(const float*)(ap + 8*144 + 16));
                #pragma unroll
                for (int nt=0; nt<8; nt++)
                    mma_tf32(acc[mt][nt], af, bf[nt][0], bf[nt][1]);
            }
        }

        if (kt+2 < 64){
            int st2 = (kt+2) - ((kt+2)/3)*3;
            load_stage(st2, kt+2);
        }
        asm volatile("cp.async.commit_group;");
        __syncthreads();
    }

    const int row0 = m0 + warp_m + (lane>>2);
    const int col0 = n0 + warp_n + ((lane&3)<<1);
    #pragma unroll
    for (int mt=0; mt<4; mt++){
        #pragma unroll
        for (int nt=0; nt<8; nt++){
            float* p0 = C + (size_t)(row0 + mt*16)*Dn + col0 + nt*8;
            float* p1 = p0 + 8*(size_t)Dn;
            *(float2*)p0 = make_float2(acc[mt][nt][0], acc[mt][nt][1]);
            *(float2*)p1 = make_float2(acc[mt][nt][2], acc[mt][nt][3]);
        }
    }
}

// ======================= RoPE tables ========================================
__global__ void build_rope_tables() {
    int idx = blockIdx.x * blockDim.x + threadIdx.x;
    if (idx >= MAXPOS*64) return;
    int pos = idx >> 6;
    int i   = idx & 63;
    float expo = (float)(2*i) * (1.0f/128.0f);
    float inv  = 1.0f / powf(10000.0f, expo);
    float ang  = (float)pos * inv;
    g_cos[idx] = cosf(ang);
    g_sin[idx] = sinf(ang);
}

// ======================= fused RoPE + hi/lo split ===========================
// Q,K: rotate + split. V: split only. One u32 (2 bf16) per array per thread.
__global__ void rope_split(const int* __restrict__ tp) {
    int idx = blockIdx.x*blockDim.x + threadIdx.x;
    const int total = Bn*Ln*Hn*64;
    if (idx >= total) return;
    int i = idx & 63;
    int h = (idx >> 6) & (Hn-1);
    int l = (idx >> 10) & (Ln-1);
    int b = idx >> 21;
    int pos = tp[b*Ln + l];
    float c = g_cos[pos*64 + i];
    float s = g_sin[pos*64 + i];
    size_t off = ((size_t)(b*Ln + l))*Dn + h*128 + 2*i;
    uint32_t hp, lp;

    float2 q = *(float2*)&g_Q[off];
    splitpack(q.x*c - q.y*s, q.x*s + q.y*c, hp, lp);
    *(uint32_t*)&g_Qh[off] = hp; *(uint32_t*)&g_Ql[off] = lp;

    float2 k = *(float2*)&g_K[off];
    splitpack(k.x*c - k.y*s, k.x*s + k.y*c, hp, lp);
    *(uint32_t*)&g_Kh[off] = hp; *(uint32_t*)&g_Kl[off] = lp;

    float2 v = *(float2*)&g_V[off];
    splitpack(v.x, v.y, hp, lp);
    *(uint32_t*)&g_Vh[off] = hp; *(uint32_t*)&g_Vl[off] = lp;
}

// ======================= tensor-core flash attention ========================
// CTA: 128 q-rows x one head. 8 warps: warp w owns q rows w*16..w*16+15.
// K/V tiles: 64 rows, hi/lo bf16, 2-stage cp.async pipeline.
// S = Q K^T and O += P V, both 3-term split-bf16 mma.sync. Softmax fp32.
#define AT_ROWB 272                          // padded row: 136 bf16 = 272 B
#define AT_KH   0
#define AT_KL   17408
#define AT_VH   34816
#define AT_VL   52224
#define AT_STAGE 69632
#define AT_QOFF (2*AT_STAGE)                 // Q staging: hi then lo
#define AT_SMEM (2*AT_STAGE + 69632)         // 208896

__global__ __launch_bounds__(256, 1)
void attn_mma(const __nv_bfloat16* __restrict__ Qh, const __nv_bfloat16* __restrict__ Ql,
              const __nv_bfloat16* __restrict__ Kh_, const __nv_bfloat16* __restrict__ Kl_,
              const __nv_bfloat16* __restrict__ Vh_, const __nv_bfloat16* __restrict__ Vl_,
              float* __restrict__ Og)
{
    extern __shared__ char sm[];
    uint32_t sb = smem_u32(sm);
    const int tid = threadIdx.x, w = tid>>5, lane = tid&31;
    const int qb = (int)(gridDim.x - 1 - blockIdx.x);     // heavy tiles first
    const int bh = blockIdx.y;
    const int b = bh>>4, h = bh&15;
    const size_t rowbase = (size_t)b*Ln;
    const size_t colb = (size_t)h*128;
    const int kmax = 2*qb + 1;

    {   // Q: 4096 16B chunks (hi 2048, lo 2048)
        #pragma unroll
        for (int j=0;j<16;j++){
            int c = tid + j*256;
            int half = c>>11, r = (c>>4)&127, seg = c&15;
            const char* src = (const char*)(half?Ql:Qh)
                + (((rowbase + (size_t)qb*128 + r)*Dn + colb)<<1) + seg*16;
            cp16(sb + AT_QOFF + half*34816 + r*AT_ROWB + seg*16, src);
        }
        asm volatile("cp.async.commit_group;");
    }
    auto issue_kv = [&](int kb2, int st){
        uint32_t sbase = sb + st*AT_STAGE;
        #pragma unroll
        for (int j=0;j<16;j++){
            int c = tid + j*256;
            int arr = c>>10, r = (c>>4)&63, seg = c&15;
            const char* base = (arr==0)?(const char*)Kh_:((arr==1)?(const char*)Kl_:
                               ((arr==2)?(const char*)Vh_:(const char*)Vl_));
            const char* src = base + (((rowbase + (size_t)kb2*64 + r)*Dn + colb)<<1) + seg*16;
            cp16(sbase + arr*17408 + r*AT_ROWB + seg*16, src);
        }
    };
    issue_kv(0, 0);
    asm volatile("cp.async.commit_group;");

    asm volatile("cp.async.wait_group 1;");
    __syncthreads();
    uint32_t qh[8][4], ql[8][4];
    {
        uint32_t qa = sb + AT_QOFF + (uint32_t)(w*16 + (lane&15))*AT_ROWB + ((lane>>4)<<4);
        #pragma unroll
        for (int ks=0; ks<8; ks++){
            ldsm4(qh[ks], qa + ks*32);
            ldsm4(ql[ks], qa + ks*32 + 34816);
        }
    }

    float o[16][4];
    #pragma unroll
    for (int i=0;i<16;i++){ o[i][0]=0.f;o[i][1]=0.f;o[i][2]=0.f;o[i][3]=0.f; }
    float m0 = -1e30f, m1 = -1e30f, l0 = 0.f, l1 = 0.f;
    const float scale = 0.08838834764831845f;
    const int grow0 = qb*128 + w*16 + (lane>>2);

    for (int kb=0; kb<=kmax; ++kb){
        __syncthreads();
        if (kb+1 <= kmax) issue_kv(kb+1, (kb+1)&1);
        asm volatile("cp.async.commit_group;");
        asm volatile("cp.async.wait_group 1;");
        __syncthreads();
        uint32_t base = sb + (uint32_t)(kb&1)*AT_STAGE;

        // ---- S = Q K^T (3-term) ----
        float s[8][4];
        #pragma unroll
        for (int j=0;j<8;j++){ s[j][0]=0.f;s[j][1]=0.f;s[j][2]=0.f;s[j][3]=0.f; }
        uint32_t kaBase = base + (uint32_t)(lane&15)*AT_ROWB + ((lane>>4)<<4);
        #pragma unroll
        for (int ks=0; ks<8; ks++){
            #pragma unroll
            for (int p2=0; p2<4; p2++){
                uint32_t ka = kaBase + (uint32_t)p2*(16*AT_ROWB) + ks*32;
                uint32_t bh4[4], bl4[4];
                ldsm4(bh4, ka + AT_KH);
                ldsm4(bl4, ka + AT_KL);
                mma16816(s[2*p2],   qh[ks], bh4[0], bh4[2]);
                mma16816(s[2*p2+1], qh[ks], bh4[1], bh4[3]);
                mma16816(s[2*p2],   qh[ks], bl4[0], bl4[2]);
                mma16816(s[2*p2+1], qh[ks], bl4[1], bl4[3]);
                mma16816(s[2*p2],   ql[ks], bh4[0], bh4[2]);
                mma16816(s[2*p2+1], ql[ks], bh4[1], bh4[3]);
            }
        }

        // ---- scale + causal mask ----
        if (kb >= 2*qb){
            #pragma unroll
            for (int j=0;j<8;j++){
                int gc = kb*64 + j*8 + ((lane&3)<<1);
                s[j][0] = (gc   <= grow0)   ? s[j][0]*scale : -1e30f;
                s[j][1] = (gc+1 <= grow0)   ? s[j][1]*scale : -1e30f;
                s[j][2] = (gc   <= grow0+8) ? s[j][2]*scale : -1e30f;
                s[j][3] = (gc+1 <= grow0+8) ? s[j][3]*scale : -1e30f;
            }
        } else {
            #pragma unroll
            for (int j=0;j<8;j++){
                s[j][0]*=scale; s[j][1]*=scale; s[j][2]*=scale; s[j][3]*=scale;
            }
        }

        // ---- online softmax ----
        float rm0 = -1e30f, rm1 = -1e30f;
        #pragma unroll
        for (int j=0;j<8;j++){
            rm0 = fmaxf(rm0, fmaxf(s[j][0], s[j][1]));
            rm1 = fmaxf(rm1, fmaxf(s[j][2], s[j][3]));
        }
        rm0 = fmaxf(rm0, __shfl_xor_sync(0xffffffffu, rm0, 1));
        rm0 = fmaxf(rm0, __shfl_xor_sync(0xffffffffu, rm0, 2));
        rm1 = fmaxf(rm1, __shfl_xor_sync(0xffffffffu, rm1, 1));
        rm1 = fmaxf(rm1, __shfl_xor_sync(0xffffffffu, rm1, 2));
        float mN0 = fmaxf(m0, rm0), mN1 = fmaxf(m1, rm1);
        float fac0 = __expf(m0 - mN0), fac1 = __expf(m1 - mN1);
        m0 = mN0; m1 = mN1;
        float rs0 = 0.f, rs1 = 0.f;
        #pragma unroll
        for (int j=0;j<8;j++){
            s[j][0] = __expf(s[j][0] - mN0);
            s[j][1] = __expf(s[j][1] - mN0);
            s[j][2] = __expf(s[j][2] - mN1);
            s[j][3] = __expf(s[j][3] - mN1);
            rs0 += s[j][0] + s[j][1];
            rs1 += s[j][2] + s[j][3];
        }
        rs0 += __shfl_xor_sync(0xffffffffu, rs0, 1);
        rs0 += __shfl_xor_sync(0xffffffffu, rs0, 2);
        rs1 += __shfl_xor_sync(0xffffffffu, rs1, 1);
        rs1 += __shfl_xor_sync(0xffffffffu, rs1, 2);
        l0 = l0*fac0 + rs0;
        l1 = l1*fac1 + rs1;
        #pragma unroll
        for (int i=0;i<16;i++){
            o[i][0]*=fac0; o[i][1]*=fac0; o[i][2]*=fac1; o[i][3]*=fac1;
        }

        // ---- O += P V (3-term) ----
        uint32_t vaBase = base + ((uint32_t)(lane&7) + (((lane>>3)&1)<<3))*AT_ROWB
                               + (((lane>>4)<<3)<<1);
        #pragma unroll
        for (int ks=0; ks<4; ks++){
            uint32_t aH[4], aL[4];
            splitpack(s[2*ks][0],   s[2*ks][1],   aH[0], aL[0]);
            splitpack(s[2*ks][2],   s[2*ks][3],   aH[1], aL[1]);
            splitpack(s[2*ks+1][0], s[2*ks+1][1], aH[2], aL[2]);
            splitpack(s[2*ks+1][2], s[2*ks+1][3], aH[3], aL[3]);
            #pragma unroll
            for (int nt2=0; nt2<8; nt2++){
                uint32_t va = vaBase + (uint32_t)ks*(16*AT_ROWB) + (uint32_t)nt2*32;
                uint32_t vh4[4], vl4[4];
                ldsm4t(vh4, va + AT_VH);
                ldsm4t(vl4, va + AT_VL);
                mma16816(o[2*nt2],   aH, vh4[0], vh4[1]);
                mma16816(o[2*nt2+1], aH, vh4[2], vh4[3]);
                mma16816(o[2*nt2],   aH, vl4[0], vl4[1]);
                mma16816(o[2*nt2+1], aH, vl4[2], vl4[3]);
                mma16816(o[2*nt2],   aL, vh4[0], vh4[1]);
                mma16816(o[2*nt2+1], aL, vh4[2], vh4[3]);
            }
        }
    }

    // ---- epilogue: normalize + fp32 store ----
    float inv0 = 1.0f/l0, inv1 = 1.0f/l1;
    size_t r0off = (rowbase + (size_t)grow0)*Dn + colb + ((lane&3)<<1);
    size_t r1off = r0off + 8*(size_t)Dn;
    #pragma unroll
    for (int nt=0; nt<16; nt++){
        *(float2*)&Og[r0off + nt*8] = make_float2(o[nt][0]*inv0, o[nt][1]*inv0);
        *(float2*)&Og[r1off + nt*8] = make_float2(o[nt][2]*inv1, o[nt][3]*inv1);
    }
}

// ======================= launch =============================================
extern "C" void kernel_launch(void* const* d_in, const int* in_sizes, int n_in,
                              void* d_out, int out_size) {
    const float* x  = (const float*)d_in[0];
    const int*   tp = (const int*)d_in[2];
    const float* Wq = (const float*)d_in[3];
    const float* Wk = (const float*)d_in[4];
    const float* Wv = (const float*)d_in[5];
    const float* Wo = (const float*)d_in[6];
    float* out = (float*)d_out;

    float *Qp, *Kp, *Vp, *Op;
    __nv_bfloat16 *Qhp,*Qlp,*Khp,*Klp,*Vhp,*Vlp;
    cudaGetSymbolAddress((void**)&Qp, g_Q);
    cudaGetSymbolAddress((void**)&Kp, g_K);
    cudaGetSymbolAddress((void**)&Vp, g_V);
    cudaGetSymbolAddress((void**)&Op, g_O);
    cudaGetSymbolAddress((void**)&Qhp, g_Qh);
    cudaGetSymbolAddress((void**)&Qlp, g_Ql);
    cudaGetSymbolAddress((void**)&Khp, g_Kh);
    cudaGetSymbolAddress((void**)&Klp, g_Kl);
    cudaGetSymbolAddress((void**)&Vhp, g_Vh);
    cudaGetSymbolAddress((void**)&Vlp, g_Vl);

    cudaFuncSetAttribute((const void*)gemm_tf32,
                         cudaFuncAttributeMaxDynamicSharedMemorySize, TG_SMEM);
    cudaFuncSetAttribute((const void*)attn_mma,
                         cudaFuncAttributeMaxDynamicSharedMemorySize, AT_SMEM);

    build_rope_tables<<<(MAXPOS*64 + 255)/256, 256>>>();

    // QKV projections (tf32, fp32 out)
    gemm_tf32<<<dim3(Dn/256, MROWS/128, 3), 256, TG_SMEM>>>(
        x, Wq, Wk, Wv, Qp, Kp, Vp);

    // fused RoPE + hi/lo bf16 split of Q,K,V
    rope_split<<<(Bn*Ln*Hn*64 + 255)/256, 256>>>(tp);

    attn_mma<<<dim3(Ln/128, Bn*Hn), 256, AT_SMEM>>>(
        Qhp, Qlp, Khp, Klp, Vhp, Vlp, Op);

    // output projection (tf32)
    gemm_tf32<<<dim3(Dn/256, MROWS/128, 1), 256, TG_SMEM>>>(
        Op, Wo, Wo, Wo, out, out, out);
}

// round 6
// speedup vs baseline: 5.5920x; 1.3965x over previous
#include <cuda_runtime.h>
#include <cuda_bf16.h>
#include <cuda_fp16.h>
#include <math.h>
#include <stdint.h>

#define Bn 2
#define Ln 2048
#define Dn 2048
#define Hn 16
#define DHn 128
#define MROWS (Bn*Ln)          // 4096
#define MAXPOS 4096

// ---------------- scratch (device globals; no allocation allowed) ----------
__device__ float g_Q[(size_t)MROWS*Dn];
__device__ float g_K[(size_t)MROWS*Dn];
__device__ float g_V[(size_t)MROWS*Dn];
__device__ __half g_xH[(size_t)MROWS*Dn];
__device__ __half g_wH[4][(size_t)Dn*Dn];
__device__ __half g_OH[(size_t)MROWS*Dn];
__device__ __nv_bfloat16 g_Qh[(size_t)MROWS*Dn];
__device__ __nv_bfloat16 g_Ql[(size_t)MROWS*Dn];
__device__ __nv_bfloat16 g_Kh[(size_t)MROWS*Dn];
__device__ __nv_bfloat16 g_Kl[(size_t)MROWS*Dn];
__device__ __nv_bfloat16 g_Vh[(size_t)MROWS*Dn];
__device__ __nv_bfloat16 g_Vl[(size_t)MROWS*Dn];
__device__ float g_cos[MAXPOS*64];
__device__ float g_sin[MAXPOS*64];

// ======================= helpers ============================================
__device__ __forceinline__ uint32_t smem_u32(const void* p){
    uint32_t a;
    asm("{ .reg .u64 t; cvta.to.shared.u64 t, %1; cvt.u32.u64 %0, t; }" : "=r"(a) : "l"(p));
    return a;
}
__device__ __forceinline__ void cp16(uint32_t s, const void* g){
    asm volatile("cp.async.cg.shared.global [%0], [%1], 16;" :: "r"(s), "l"(g));
}
__device__ __forceinline__ void ldsm4(uint32_t* r, uint32_t a){
    asm volatile("ldmatrix.sync.aligned.m8n8.x4.shared.b16 {%0,%1,%2,%3},[%4];"
        : "=r"(r[0]),"=r"(r[1]),"=r"(r[2]),"=r"(r[3]) : "r"(a));
}
__device__ __forceinline__ void ldsm4t(uint32_t* r, uint32_t a){
    asm volatile("ldmatrix.sync.aligned.m8n8.x4.trans.shared.b16 {%0,%1,%2,%3},[%4];"
        : "=r"(r[0]),"=r"(r[1]),"=r"(r[2]),"=r"(r[3]) : "r"(a));
}
__device__ __forceinline__ void mma16816(float* c, const uint32_t* a, uint32_t b0, uint32_t b1){
    asm volatile("mma.sync.aligned.m16n8k16.row.col.f32.bf16.bf16.f32 "
        "{%0,%1,%2,%3},{%4,%5,%6,%7},{%8,%9},{%0,%1,%2,%3};"
        : "+f"(c[0]),"+f"(c[1]),"+f"(c[2]),"+f"(c[3])
        : "r"(a[0]),"r"(a[1]),"r"(a[2]),"r"(a[3]),"r"(b0),"r"(b1));
}
__device__ __forceinline__ void mma_f16(float* c, const uint32_t* a, uint32_t b0, uint32_t b1){
    asm volatile("mma.sync.aligned.m16n8k16.row.col.f32.f16.f16.f32 "
        "{%0,%1,%2,%3},{%4,%5,%6,%7},{%8,%9},{%0,%1,%2,%3};"
        : "+f"(c[0]),"+f"(c[1]),"+f"(c[2]),"+f"(c[3])
        : "r"(a[0]),"r"(a[1]),"r"(a[2]),"r"(a[3]),"r"(b0),"r"(b1));
}
__device__ __forceinline__ uint32_t pack2(__nv_bfloat16 a, __nv_bfloat16 b){
    return ((uint32_t)__bfloat16_as_ushort(b)<<16) | (uint32_t)__bfloat16_as_ushort(a);
}
__device__ __forceinline__ void splitpack(float x, float y, uint32_t& hp, uint32_t& lp){
    __nv_bfloat16 hx=__float2bfloat16(x), hy=__float2bfloat16(y);
    __nv_bfloat16 lx=__float2bfloat16(x-__bfloat162float(hx));
    __nv_bfloat16 ly=__float2bfloat16(y-__bfloat162float(hy));
    hp = pack2(hx,hy); lp = pack2(lx,ly);
}
__device__ __forceinline__ uint32_t packh2(float x, float y){
    __half2 h = __floats2half2_rn(x, y);
    return *(uint32_t*)&h;
}

// ======================= f32 -> fp16 conversion =============================
__global__ void conv_f16(const float* __restrict__ src, __half* __restrict__ dst, int n4){
    int i = blockIdx.x*blockDim.x + threadIdx.x;
    if (i >= n4) return;
    float4 v = ((const float4*)src)[i];
    ((uint2*)dst)[i] = make_uint2(packh2(v.x,v.y), packh2(v.z,v.w));
}

// ======================= fp16 mma.sync GEMM =================================
// C[m,n] = sum_k A[m,k]*W[n,k], K=2048, fp16 in, fp32 accum/out.
// CTA 128x256, BK=32, 8 warps (2x4), warp tile 64x64, 3-stage cp.async.
#define FSW     10240
#define FSTAGE  30720
#define FG_SMEM (3*FSTAGE)   // 92160

__global__ __launch_bounds__(256)
void gemm_fp16(const __half* __restrict__ A,
               const __half* __restrict__ W0, const __half* __restrict__ W1, const __half* __restrict__ W2,
               float* __restrict__ C0, float* __restrict__ C1, float* __restrict__ C2)
{
    extern __shared__ char smem[];
    uint32_t sb = smem_u32(smem);
    const int tid = threadIdx.x, wid = tid>>5, lane = tid&31;
    const int z = blockIdx.z;
    const __half* W = (z==0)?W0:((z==1)?W1:W2);
    float*       C = (z==0)?C0:((z==1)?C1:C2);
    const int m0 = blockIdx.y*128, n0 = blockIdx.x*256;
    const int warp_m = (wid>>2)*64, warp_n = (wid&3)*64;

    auto load_stage = [&](int st, int kt){
        uint32_t sbase = sb + st*FSTAGE;
        #pragma unroll
        for (int j=0;j<6;j++){
            int c = tid + j*256;
            if (c < 512){
                int row = c>>2, seg = c&3;
                cp16(sbase + row*80 + seg*16,
                     A + (size_t)(m0+row)*Dn + kt*32 + seg*8);
            } else {
                int cc = c - 512; int row = cc>>2, seg = cc&3;
                cp16(sbase + FSW + row*80 + seg*16,
                     W + (size_t)(n0+row)*Dn + kt*32 + seg*8);
            }
        }
    };

    float acc[4][8][4];
    #pragma unroll
    for (int i=0;i<4;i++)
        #pragma unroll
        for (int j=0;j<8;j++)
            #pragma unroll
            for (int q=0;q<4;q++) acc[i][j][q]=0.f;

    load_stage(0, 0);
    asm volatile("cp.async.commit_group;");
    load_stage(1, 1);
    asm volatile("cp.async.commit_group;");

    const int lrow = lane & 15;
    const uint32_t lcolB = (uint32_t)((lane>>4)<<4);

    for (int kt=0; kt<64; ++kt){
        int st = kt - (kt/3)*3;
        uint32_t base = sb + st*FSTAGE;
        asm volatile("cp.async.wait_group 1;");
        __syncthreads();

        #pragma unroll
        for (int ks=0; ks<2; ++ks){
            uint32_t kB = ks*32;
            uint32_t aAddr = base + (uint32_t)(warp_m + lrow)*80 + lcolB + kB;
            uint32_t wAddr = base + FSW + (uint32_t)(warp_n + lrow)*80 + lcolB + kB;

            uint32_t ahr[4][4], whr[4][4];
            #pragma unroll
            for (int mt=0; mt<4; mt++) ldsm4(ahr[mt], aAddr + mt*(16*80));
            #pragma unroll
            for (int p=0; p<4; p++)   ldsm4(whr[p], wAddr + p*(16*80));
            #pragma unroll
            for (int mt=0; mt<4; mt++)
                #pragma unroll
                for (int p=0; p<4; p++){
                    mma_f16(acc[mt][2*p],   ahr[mt], whr[p][0], whr[p][2]);
                    mma_f16(acc[mt][2*p+1], ahr[mt], whr[p][1], whr[p][3]);
                }
        }

        if (kt+2 < 64){
            int st2 = (kt+2) - ((kt+2)/3)*3;
            load_stage(st2, kt+2);
        }
        asm volatile("cp.async.commit_group;");
        __syncthreads();
    }

    const int row0 = m0 + warp_m + (lane>>2);
    const int col0 = n0 + warp_n + ((lane&3)<<1);
    #pragma unroll
    for (int mt=0; mt<4; mt++){
        #pragma unroll
        for (int nt=0; nt<8; nt++){
            float* p0 = C + (size_t)(row0 + mt*16)*Dn + col0 + nt*8;
            float* p1 = p0 + 8*(size_t)Dn;
            *(float2*)p0 = make_float2(acc[mt][nt][0], acc[mt][nt][1]);
            *(float2*)p1 = make_float2(acc[mt][nt][2], acc[mt][nt][3]);
        }
    }
}

// ======================= RoPE tables ========================================
__global__ void build_rope_tables() {
    int idx = blockIdx.x * blockDim.x + threadIdx.x;
    if (idx >= MAXPOS*64) return;
    int pos = idx >> 6;
    int i   = idx & 63;
    float expo = (float)(2*i) * (1.0f/128.0f);
    float inv  = 1.0f / powf(10000.0f, expo);
    float ang  = (float)pos * inv;
    g_cos[idx] = cosf(ang);
    g_sin[idx] = sinf(ang);
}

// ======================= fused RoPE + hi/lo split ===========================
__global__ void rope_split(const int* __restrict__ tp) {
    int idx = blockIdx.x*blockDim.x + threadIdx.x;
    const int total = Bn*Ln*Hn*64;
    if (idx >= total) return;
    int i = idx & 63;
    int h = (idx >> 6) & (Hn-1);
    int l = (idx >> 10) & (Ln-1);
    int b = idx >> 21;
    int pos = tp[b*Ln + l];
    float c = g_cos[pos*64 + i];
    float s = g_sin[pos*64 + i];
    size_t off = ((size_t)(b*Ln + l))*Dn + h*128 + 2*i;
    uint32_t hp, lp;

    float2 q = *(float2*)&g_Q[off];
    splitpack(q.x*c - q.y*s, q.x*s + q.y*c, hp, lp);
    *(uint32_t*)&g_Qh[off] = hp; *(uint32_t*)&g_Ql[off] = lp;

    float2 k = *(float2*)&g_K[off];
    splitpack(k.x*c - k.y*s, k.x*s + k.y*c, hp, lp);
    *(uint32_t*)&g_Kh[off] = hp; *(uint32_t*)&g_Kl[off] = lp;

    float2 v = *(float2*)&g_V[off];
    splitpack(v.x, v.y, hp, lp);
    *(uint32_t*)&g_Vh[off] = hp; *(uint32_t*)&g_Vl[off] = lp;
}

// ======================= tensor-core flash attention ========================
// CTA: 128 q-rows x one head. 8 warps. K/V tiles 64 rows hi/lo bf16,
// 2-stage cp.async. 3-term split-bf16 mma.sync. Softmax fp32.
#define AT_ROWB 272
#define AT_KH   0
#define AT_KL   17408
#define AT_VH   34816
#define AT_VL   52224
#define AT_STAGE 69632
#define AT_QOFF (2*AT_STAGE)
#define AT_SMEM (2*AT_STAGE + 69632)         // 208896

__global__ __launch_bounds__(256, 1)
void attn_mma(const __nv_bfloat16* __restrict__ Qh, const __nv_bfloat16* __restrict__ Ql,
              const __nv_bfloat16* __restrict__ Kh_, const __nv_bfloat16* __restrict__ Kl_,
              const __nv_bfloat16* __restrict__ Vh_, const __nv_bfloat16* __restrict__ Vl_,
              __half* __restrict__ OgH)
{
    extern __shared__ char sm[];
    uint32_t sb = smem_u32(sm);
    const int tid = threadIdx.x, w = tid>>5, lane = tid&31;
    const int qb = (int)(gridDim.x - 1 - blockIdx.x);
    const int bh = blockIdx.y;
    const int b = bh>>4, h = bh&15;
    const size_t rowbase = (size_t)b*Ln;
    const size_t colb = (size_t)h*128;
    const int kmax = 2*qb + 1;

    {
        #pragma unroll
        for (int j=0;j<16;j++){
            int c = tid + j*256;
            int half = c>>11, r = (c>>4)&127, seg = c&15;
            const char* src = (const char*)(half?Ql:Qh)
                + (((rowbase + (size_t)qb*128 + r)*Dn + colb)<<1) + seg*16;
            cp16(sb + AT_QOFF + half*34816 + r*AT_ROWB + seg*16, src);
        }
        asm volatile("cp.async.commit_group;");
    }
    auto issue_kv = [&](int kb2, int st){
        uint32_t sbase = sb + st*AT_STAGE;
        #pragma unroll
        for (int j=0;j<16;j++){
            int c = tid + j*256;
            int arr = c>>10, r = (c>>4)&63, seg = c&15;
            const char* base = (arr==0)?(const char*)Kh_:((arr==1)?(const char*)Kl_:
                               ((arr==2)?(const char*)Vh_:(const char*)Vl_));
            const char* src = base + (((rowbase + (size_t)kb2*64 + r)*Dn + colb)<<1) + seg*16;
            cp16(sbase + arr*17408 + r*AT_ROWB + seg*16, src);
        }
    };
    issue_kv(0, 0);
    asm volatile("cp.async.commit_group;");

    asm volatile("cp.async.wait_group 1;");
    __syncthreads();
    uint32_t qh[8][4], ql[8][4];
    {
        uint32_t qa = sb + AT_QOFF + (uint32_t)(w*16 + (lane&15))*AT_ROWB + ((lane>>4)<<4);
        #pragma unroll
        for (int ks=0; ks<8; ks++){
            ldsm4(qh[ks], qa + ks*32);
            ldsm4(ql[ks], qa + ks*32 + 34816);
        }
    }

    float o[16][4];
    #pragma unroll
    for (int i=0;i<16;i++){ o[i][0]=0.f;o[i][1]=0.f;o[i][2]=0.f;o[i][3]=0.f; }
    float m0 = -1e30f, m1 = -1e30f, l0 = 0.f, l1 = 0.f;
    const float scale = 0.08838834764831845f;
    const int grow0 = qb*128 + w*16 + (lane>>2);

    for (int kb=0; kb<=kmax; ++kb){
        __syncthreads();
        if (kb+1 <= kmax) issue_kv(kb+1, (kb+1)&1);
        asm volatile("cp.async.commit_group;");
        asm volatile("cp.async.wait_group 1;");
        __syncthreads();
        uint32_t base = sb + (uint32_t)(kb&1)*AT_STAGE;

        float s[8][4];
        #pragma unroll
        for (int j=0;j<8;j++){ s[j][0]=0.f;s[j][1]=0.f;s[j][2]=0.f;s[j][3]=0.f; }
        uint32_t kaBase = base + (uint32_t)(lane&15)*AT_ROWB + ((lane>>4)<<4);
        #pragma unroll
        for (int ks=0; ks<8; ks++){
            #pragma unroll
            for (int p2=0; p2<4; p2++){
                uint32_t ka = kaBase + (uint32_t)p2*(16*AT_ROWB) + ks*32;
                uint32_t bh4[4], bl4[4];
                ldsm4(bh4, ka + AT_KH);
                ldsm4(bl4, ka + AT_KL);
                mma16816(s[2*p2],   qh[ks], bh4[0], bh4[2]);
                mma16816(s[2*p2+1], qh[ks], bh4[1], bh4[3]);
                mma16816(s[2*p2],   qh[ks], bl4[0], bl4[2]);
                mma16816(s[2*p2+1], qh[ks], bl4[1], bl4[3]);
                mma16816(s[2*p2],   ql[ks], bh4[0], bh4[2]);
                mma16816(s[2*p2+1], ql[ks], bh4[1], bh4[3]);
            }
        }

        if (kb >= 2*qb){
            #pragma unroll
            for (int j=0;j<8;j++){
                int gc = kb*64 + j*8 + ((lane&3)<<1);
                s[j][0] = (gc   <= grow0)   ? s[j][0]*scale : -1e30f;
                s[j][1] = (gc+1 <= grow0)   ? s[j][1]*scale : -1e30f;
                s[j][2] = (gc   <= grow0+8) ? s[j][2]*scale : -1e30f;
                s[j][3] = (gc+1 <= grow0+8) ? s[j][3]*scale : -1e30f;
            }
        } else {
            #pragma unroll
            for (int j=0;j<8;j++){
                s[j][0]*=scale; s[j][1]*=scale; s[j][2]*=scale; s[j][3]*=scale;
            }
        }

        float rm0 = -1e30f, rm1 = -1e30f;
        #pragma unroll
        for (int j=0;j<8;j++){
            rm0 = fmaxf(rm0, fmaxf(s[j][0], s[j][1]));
            rm1 = fmaxf(rm1, fmaxf(s[j][2], s[j][3]));
        }
        rm0 = fmaxf(rm0, __shfl_xor_sync(0xffffffffu, rm0, 1));
        rm0 = fmaxf(rm0, __shfl_xor_sync(0xffffffffu, rm0, 2));
        rm1 = fmaxf(rm1, __shfl_xor_sync(0xffffffffu, rm1, 1));
        rm1 = fmaxf(rm1, __shfl_xor_sync(0xffffffffu, rm1, 2));
        float mN0 = fmaxf(m0, rm0), mN1 = fmaxf(m1, rm1);
        float fac0 = __expf(m0 - mN0), fac1 = __expf(m1 - mN1);
        m0 = mN0; m1 = mN1;
        float rs0 = 0.f, rs1 = 0.f;
        #pragma unroll
        for (int j=0;j<8;j++){
            s[j][0] = __expf(s[j][0] - mN0);
            s[j][1] = __expf(s[j][1] - mN0);
            s[j][2] = __expf(s[j][2] - mN1);
            s[j][3] = __expf(s[j][3] - mN1);
            rs0 += s[j][0] + s[j][1];
            rs1 += s[j][2] + s[j][3];
        }
        rs0 += __shfl_xor_sync(0xffffffffu, rs0, 1);
        rs0 += __shfl_xor_sync(0xffffffffu, rs0, 2);
        rs1 += __shfl_xor_sync(0xffffffffu, rs1, 1);
        rs1 += __shfl_xor_sync(0xffffffffu, rs1, 2);
        l0 = l0*fac0 + rs0;
        l1 = l1*fac1 + rs1;
        #pragma unroll
        for (int i=0;i<16;i++){
            o[i][0]*=fac0; o[i][1]*=fac0; o[i][2]*=fac1; o[i][3]*=fac1;
        }

        uint32_t vaBase = base + ((uint32_t)(lane&7) + (((lane>>3)&1)<<3))*AT_ROWB
                               + (((lane>>4)<<3)<<1);
        #pragma unroll
        for (int ks=0; ks<4; ks++){
            uint32_t aH[4], aL[4];
            splitpack(s[2*ks][0],   s[2*ks][1],   aH[0], aL[0]);
            splitpack(s[2*ks][2],   s[2*ks][3],   aH[1], aL[1]);
            splitpack(s[2*ks+1][0], s[2*ks+1][1], aH[2], aL[2]);
            splitpack(s[2*ks+1][2], s[2*ks+1][3], aH[3], aL[3]);
            #pragma unroll
            for (int nt2=0; nt2<8; nt2++){
                uint32_t va = vaBase + (uint32_t)ks*(16*AT_ROWB) + (uint32_t)nt2*32;
                uint32_t vh4[4], vl4[4];
                ldsm4t(vh4, va + AT_VH);
                ldsm4t(vl4, va + AT_VL);
                mma16816(o[2*nt2],   aH, vh4[0], vh4[1]);
                mma16816(o[2*nt2+1], aH, vh4[2], vh4[3]);
                mma16816(o[2*nt2],   aH, vl4[0], vl4[1]);
                mma16816(o[2*nt2+1], aH, vl4[2], vl4[3]);
                mma16816(o[2*nt2],   aL, vh4[0], vh4[1]);
                mma16816(o[2*nt2+1], aL, vh4[2], vh4[3]);
            }
        }
    }

    // ---- epilogue: normalize + fp16 store ----
    float inv0 = 1.0f/l0, inv1 = 1.0f/l1;
    size_t r0off = (rowbase + (size_t)grow0)*Dn + colb + ((lane&3)<<1);
    size_t r1off = r0off + 8*(size_t)Dn;
    #pragma unroll
    for (int nt=0; nt<16; nt++){
        *(uint32_t*)&OgH[r0off + nt*8] = packh2(o[nt][0]*inv0, o[nt][1]*inv0);
        *(uint32_t*)&OgH[r1off + nt*8] = packh2(o[nt][2]*inv1, o[nt][3]*inv1);
    }
}

// ======================= launch =============================================
extern "C" void kernel_launch(void* const* d_in, const int* in_sizes, int n_in,
                              void* d_out, int out_size) {
    const float* x  = (const float*)d_in[0];
    const int*   tp = (const int*)d_in[2];
    const float* Wq = (const float*)d_in[3];
    const float* Wk = (const float*)d_in[4];
    const float* Wv = (const float*)d_in[5];
    const float* Wo = (const float*)d_in[6];
    float* out = (float*)d_out;

    float *Qp, *Kp, *Vp;
    __half *xH, *wH, *OH;
    __nv_bfloat16 *Qhp,*Qlp,*Khp,*Klp,*Vhp,*Vlp;
    cudaGetSymbolAddress((void**)&Qp, g_Q);
    cudaGetSymbolAddress((void**)&Kp, g_K);
    cudaGetSymbolAddress((void**)&Vp, g_V);
    cudaGetSymbolAddress((void**)&xH, g_xH);
    cudaGetSymbolAddress((void**)&wH, g_wH);
    cudaGetSymbolAddress((void**)&OH, g_OH);
    cudaGetSymbolAddress((void**)&Qhp, g_Qh);
    cudaGetSymbolAddress((void**)&Qlp, g_Ql);
    cudaGetSymbolAddress((void**)&Khp, g_Kh);
    cudaGetSymbolAddress((void**)&Klp, g_Kl);
    cudaGetSymbolAddress((void**)&Vhp, g_Vh);
    cudaGetSymbolAddress((void**)&Vlp, g_Vl);
    const size_t WS = (size_t)Dn*Dn;

    cudaFuncSetAttribute((const void*)gemm_fp16,
                         cudaFuncAttributeMaxDynamicSharedMemorySize, FG_SMEM);
    cudaFuncSetAttribute((const void*)attn_mma,
                         cudaFuncAttributeMaxDynamicSharedMemorySize, AT_SMEM);

    build_rope_tables<<<(MAXPOS*64 + 255)/256, 256>>>();

    // convert inputs to fp16
    const int n4x = MROWS*Dn/4, n4w = Dn*Dn/4;
    conv_f16<<<(n4x+255)/256, 256>>>(x,  xH,      n4x);
    conv_f16<<<(n4w+255)/256, 256>>>(Wq, wH+0*WS, n4w);
    conv_f16<<<(n4w+255)/256, 256>>>(Wk, wH+1*WS, n4w);
    conv_f16<<<(n4w+255)/256, 256>>>(Wv, wH+2*WS, n4w);
    conv_f16<<<(n4w+255)/256, 256>>>(Wo, wH+3*WS, n4w);

    // QKV projections (fp16 MMA, fp32 out)
    gemm_fp16<<<dim3(Dn/256, MROWS/128, 3), 256, FG_SMEM>>>(
        xH, wH+0*WS, wH+1*WS, wH+2*WS, Qp, Kp, Vp);

    // fused RoPE + hi/lo bf16 split of Q,K,V
    rope_split<<<(Bn*Ln*Hn*64 + 255)/256, 256>>>(tp);

    attn_mma<<<dim3(Ln/128, Bn*Hn), 256, AT_SMEM>>>(
        Qhp, Qlp, Khp, Klp, Vhp, Vlp, OH);

    // output projection (fp16 MMA)
    gemm_fp16<<<dim3(Dn/256, MROWS/128, 1), 256, FG_SMEM>>>(
        OH, wH+3*WS, wH+3*WS, wH+3*WS, out, out, out);
}

// round 7
// speedup vs baseline: 7.0477x; 1.2603x over previous
#include <cuda_runtime.h>
#include <cuda_bf16.h>
#include <cuda_fp16.h>
#include <math.h>
#include <stdint.h>

#define Bn 2
#define Ln 2048
#define Dn 2048
#define Hn 16
#define DHn 128
#define MROWS (Bn*Ln)          // 4096
#define MAXPOS 4096

// ---------------- scratch (device globals; no allocation allowed) ----------
__device__ float g_Q[(size_t)MROWS*Dn];
__device__ float g_K[(size_t)MROWS*Dn];
__device__ float g_V[(size_t)MROWS*Dn];
__device__ __half g_xH[(size_t)MROWS*Dn];
__device__ __half g_wH[4][(size_t)Dn*Dn];
__device__ __half g_OH[(size_t)MROWS*Dn];
__device__ __half g_Qf[(size_t)MROWS*Dn];
__device__ __half g_Kf[(size_t)MROWS*Dn];
__device__ __half g_Vf[(size_t)MROWS*Dn];
__device__ float g_cos[MAXPOS*64];
__device__ float g_sin[MAXPOS*64];

// ======================= helpers ============================================
__device__ __forceinline__ uint32_t smem_u32(const void* p){
    uint32_t a;
    asm("{ .reg .u64 t; cvta.to.shared.u64 t, %1; cvt.u32.u64 %0, t; }" : "=r"(a) : "l"(p));
    return a;
}
__device__ __forceinline__ void cp16(uint32_t s, const void* g){
    asm volatile("cp.async.cg.shared.global [%0], [%1], 16;" :: "r"(s), "l"(g));
}
__device__ __forceinline__ void ldsm4(uint32_t* r, uint32_t a){
    asm volatile("ldmatrix.sync.aligned.m8n8.x4.shared.b16 {%0,%1,%2,%3},[%4];"
        : "=r"(r[0]),"=r"(r[1]),"=r"(r[2]),"=r"(r[3]) : "r"(a));
}
__device__ __forceinline__ void ldsm4t(uint32_t* r, uint32_t a){
    asm volatile("ldmatrix.sync.aligned.m8n8.x4.trans.shared.b16 {%0,%1,%2,%3},[%4];"
        : "=r"(r[0]),"=r"(r[1]),"=r"(r[2]),"=r"(r[3]) : "r"(a));
}
__device__ __forceinline__ void mma_f16(float* c, const uint32_t* a, uint32_t b0, uint32_t b1){
    asm volatile("mma.sync.aligned.m16n8k16.row.col.f32.f16.f16.f32 "
        "{%0,%1,%2,%3},{%4,%5,%6,%7},{%8,%9},{%0,%1,%2,%3};"
        : "+f"(c[0]),"+f"(c[1]),"+f"(c[2]),"+f"(c[3])
        : "r"(a[0]),"r"(a[1]),"r"(a[2]),"r"(a[3]),"r"(b0),"r"(b1));
}
__device__ __forceinline__ uint32_t packh2(float x, float y){
    __half2 h = __floats2half2_rn(x, y);
    return *(uint32_t*)&h;
}

// ======================= f32 -> fp16 conversion =============================
__global__ void conv_f16(const float* __restrict__ src, __half* __restrict__ dst, int n4){
    int i = blockIdx.x*blockDim.x + threadIdx.x;
    if (i >= n4) return;
    float4 v = ((const float4*)src)[i];
    ((uint2*)dst)[i] = make_uint2(packh2(v.x,v.y), packh2(v.z,v.w));
}

// ======================= fp16 mma.sync GEMM =================================
// C[m,n] = sum_k A[m,k]*W[n,k], K=2048, fp16 in, fp32 accum/out.
// CTA 128x256, BK=32, 8 warps (2x4), warp tile 64x64, 3-stage cp.async.
#define FSW     10240
#define FSTAGE  30720
#define FG_SMEM (3*FSTAGE)   // 92160

__global__ __launch_bounds__(256)
void gemm_fp16(const __half* __restrict__ A,
               const __half* __restrict__ W0, const __half* __restrict__ W1, const __half* __restrict__ W2,
               float* __restrict__ C0, float* __restrict__ C1, float* __restrict__ C2)
{
    extern __shared__ char smem[];
    uint32_t sb = smem_u32(smem);
    const int tid = threadIdx.x, wid = tid>>5, lane = tid&31;
    const int z = blockIdx.z;
    const __half* W = (z==0)?W0:((z==1)?W1:W2);
    float*       C = (z==0)?C0:((z==1)?C1:C2);
    const int m0 = blockIdx.y*128, n0 = blockIdx.x*256;
    const int warp_m = (wid>>2)*64, warp_n = (wid&3)*64;

    auto load_stage = [&](int st, int kt){
        uint32_t sbase = sb + st*FSTAGE;
        #pragma unroll
        for (int j=0;j<6;j++){
            int c = tid + j*256;
            if (c < 512){
                int row = c>>2, seg = c&3;
                cp16(sbase + row*80 + seg*16,
                     A + (size_t)(m0+row)*Dn + kt*32 + seg*8);
            } else {
                int cc = c - 512; int row = cc>>2, seg = cc&3;
                cp16(sbase + FSW + row*80 + seg*16,
                     W + (size_t)(n0+row)*Dn + kt*32 + seg*8);
            }
        }
    };

    float acc[4][8][4];
    #pragma unroll
    for (int i=0;i<4;i++)
        #pragma unroll
        for (int j=0;j<8;j++)
            #pragma unroll
            for (int q=0;q<4;q++) acc[i][j][q]=0.f;

    load_stage(0, 0);
    asm volatile("cp.async.commit_group;");
    load_stage(1, 1);
    asm volatile("cp.async.commit_group;");

    const int lrow = lane & 15;
    const uint32_t lcolB = (uint32_t)((lane>>4)<<4);

    for (int kt=0; kt<64; ++kt){
        int st = kt - (kt/3)*3;
        uint32_t base = sb + st*FSTAGE;
        asm volatile("cp.async.wait_group 1;");
        __syncthreads();

        #pragma unroll
        for (int ks=0; ks<2; ++ks){
            uint32_t kB = ks*32;
            uint32_t aAddr = base + (uint32_t)(warp_m + lrow)*80 + lcolB + kB;
            uint32_t wAddr = base + FSW + (uint32_t)(warp_n + lrow)*80 + lcolB + kB;

            uint32_t ahr[4][4], whr[4][4];
            #pragma unroll
            for (int mt=0; mt<4; mt++) ldsm4(ahr[mt], aAddr + mt*(16*80));
            #pragma unroll
            for (int p=0; p<4; p++)   ldsm4(whr[p], wAddr + p*(16*80));
            #pragma unroll
            for (int mt=0; mt<4; mt++)
                #pragma unroll
                for (int p=0; p<4; p++){
                    mma_f16(acc[mt][2*p],   ahr[mt], whr[p][0], whr[p][2]);
                    mma_f16(acc[mt][2*p+1], ahr[mt], whr[p][1], whr[p][3]);
                }
        }

        if (kt+2 < 64){
            int st2 = (kt+2) - ((kt+2)/3)*3;
            load_stage(st2, kt+2);
        }
        asm volatile("cp.async.commit_group;");
        __syncthreads();
    }

    const int row0 = m0 + warp_m + (lane>>2);
    const int col0 = n0 + warp_n + ((lane&3)<<1);
    #pragma unroll
    for (int mt=0; mt<4; mt++){
        #pragma unroll
        for (int nt=0; nt<8; nt++){
            float* p0 = C + (size_t)(row0 + mt*16)*Dn + col0 + nt*8;
            float* p1 = p0 + 8*(size_t)Dn;
            *(float2*)p0 = make_float2(acc[mt][nt][0], acc[mt][nt][1]);
            *(float2*)p1 = make_float2(acc[mt][nt][2], acc[mt][nt][3]);
        }
    }
}

// ======================= RoPE tables ========================================
__global__ void build_rope_tables() {
    int idx = blockIdx.x * blockDim.x + threadIdx.x;
    if (idx >= MAXPOS*64) return;
    int pos = idx >> 6;
    int i   = idx & 63;
    float expo = (float)(2*i) * (1.0f/128.0f);
    float inv  = 1.0f / powf(10000.0f, expo);
    float ang  = (float)pos * inv;
    g_cos[idx] = cosf(ang);
    g_sin[idx] = sinf(ang);
}

// ======================= fused RoPE + fp16 convert ==========================
// Q,K: rotate then fp16. V: fp16 only.
__global__ void rope_conv(const int* __restrict__ tp) {
    int idx = blockIdx.x*blockDim.x + threadIdx.x;
    const int total = Bn*Ln*Hn*64;
    if (idx >= total) return;
    int i = idx & 63;
    int h = (idx >> 6) & (Hn-1);
    int l = (idx >> 10) & (Ln-1);
    int b = idx >> 21;
    int pos = tp[b*Ln + l];
    float c = g_cos[pos*64 + i];
    float s = g_sin[pos*64 + i];
    size_t off = ((size_t)(b*Ln + l))*Dn + h*128 + 2*i;

    float2 q = *(float2*)&g_Q[off];
    *(uint32_t*)&g_Qf[off] = packh2(q.x*c - q.y*s, q.x*s + q.y*c);
    float2 k = *(float2*)&g_K[off];
    *(uint32_t*)&g_Kf[off] = packh2(k.x*c - k.y*s, k.x*s + k.y*c);
    float2 v = *(float2*)&g_V[off];
    *(uint32_t*)&g_Vf[off] = packh2(v.x, v.y);
}

// ======================= fp16 tensor-core flash attention ===================
// CTA: 128 q-rows x one head. 8 warps: warp w owns q rows w*16..w*16+15.
// K/V tiles: 64 rows fp16, 2-stage cp.async pipeline. Single-term fp16 MMA.
#define AT_ROWB 272                          // padded row: 136 fp16 = 272 B
#define AT_K    0
#define AT_V    17408
#define AT_STAGE 34816
#define AT_QOFF (2*AT_STAGE)                 // 69632
#define AT_SMEM (2*AT_STAGE + 34816)         // 104448

__global__ __launch_bounds__(256, 1)
void attn_mma(const __half* __restrict__ Qg, const __half* __restrict__ Kg,
              const __half* __restrict__ Vg, __half* __restrict__ OgH)
{
    extern __shared__ char sm[];
    uint32_t sb = smem_u32(sm);
    const int tid = threadIdx.x, w = tid>>5, lane = tid&31;
    const int qb = (int)(gridDim.x - 1 - blockIdx.x);     // heavy tiles first
    const int bh = blockIdx.y;
    const int b = bh>>4, h = bh&15;
    const size_t rowbase = (size_t)b*Ln;
    const size_t colb = (size_t)h*128;
    const int kmax = 2*qb + 1;

    {   // Q: 2048 16B chunks (128 rows x 256 B)
        #pragma unroll
        for (int j=0;j<8;j++){
            int c = tid + j*256;
            int r = c>>4, seg = c&15;
            const char* src = (const char*)Qg
                + (((rowbase + (size_t)qb*128 + r)*Dn + colb)<<1) + seg*16;
            cp16(sb + AT_QOFF + r*AT_ROWB + seg*16, src);
        }
        asm volatile("cp.async.commit_group;");
    }
    auto issue_kv = [&](int kb2, int st){
        uint32_t sbase = sb + st*AT_STAGE;
        #pragma unroll
        for (int j=0;j<8;j++){
            int c = tid + j*256;
            int arr = c>>10, r = (c>>4)&63, seg = c&15;
            const char* base = arr ? (const char*)Vg : (const char*)Kg;
            const char* src = base + (((rowbase + (size_t)kb2*64 + r)*Dn + colb)<<1) + seg*16;
            cp16(sbase + arr*17408 + r*AT_ROWB + seg*16, src);
        }
    };
    issue_kv(0, 0);
    asm volatile("cp.async.commit_group;");

    // ---- Q fragments to registers (persistent) ----
    asm volatile("cp.async.wait_group 1;");
    __syncthreads();
    uint32_t qf[8][4];
    {
        uint32_t qa = sb + AT_QOFF + (uint32_t)(w*16 + (lane&15))*AT_ROWB + ((lane>>4)<<4);
        #pragma unroll
        for (int ks=0; ks<8; ks++) ldsm4(qf[ks], qa + ks*32);
    }

    float o[16][4];
    #pragma unroll
    for (int i=0;i<16;i++){ o[i][0]=0.f;o[i][1]=0.f;o[i][2]=0.f;o[i][3]=0.f; }
    float m0 = -1e30f, m1 = -1e30f, l0 = 0.f, l1 = 0.f;
    const float scale = 0.08838834764831845f;
    const int grow0 = qb*128 + w*16 + (lane>>2);

    for (int kb=0; kb<=kmax; ++kb){
        __syncthreads();
        if (kb+1 <= kmax) issue_kv(kb+1, (kb+1)&1);
        asm volatile("cp.async.commit_group;");
        asm volatile("cp.async.wait_group 1;");
        __syncthreads();
        uint32_t base = sb + (uint32_t)(kb&1)*AT_STAGE;

        // ---- S = Q K^T ----
        float s[8][4];
        #pragma unroll
        for (int j=0;j<8;j++){ s[j][0]=0.f;s[j][1]=0.f;s[j][2]=0.f;s[j][3]=0.f; }
        uint32_t kaBase = base + AT_K + (uint32_t)(lane&15)*AT_ROWB + ((lane>>4)<<4);
        #pragma unroll
        for (int ks=0; ks<8; ks++){
            #pragma unroll
            for (int p2=0; p2<4; p2++){
                uint32_t kf[4];
                ldsm4(kf, kaBase + (uint32_t)p2*(16*AT_ROWB) + ks*32);
                mma_f16(s[2*p2],   qf[ks], kf[0], kf[2]);
                mma_f16(s[2*p2+1], qf[ks], kf[1], kf[3]);
            }
        }

        // ---- scale + causal mask ----
        if (kb >= 2*qb){
            #pragma unroll
            for (int j=0;j<8;j++){
                int gc = kb*64 + j*8 + ((lane&3)<<1);
                s[j][0] = (gc   <= grow0)   ? s[j][0]*scale : -1e30f;
                s[j][1] = (gc+1 <= grow0)   ? s[j][1]*scale : -1e30f;
                s[j][2] = (gc   <= grow0+8) ? s[j][2]*scale : -1e30f;
                s[j][3] = (gc+1 <= grow0+8) ? s[j][3]*scale : -1e30f;
            }
        } else {
            #pragma unroll
            for (int j=0;j<8;j++){
                s[j][0]*=scale; s[j][1]*=scale; s[j][2]*=scale; s[j][3]*=scale;
            }
        }

        // ---- online softmax ----
        float rm0 = -1e30f, rm1 = -1e30f;
        #pragma unroll
        for (int j=0;j<8;j++){
            rm0 = fmaxf(rm0, fmaxf(s[j][0], s[j][1]));
            rm1 = fmaxf(rm1, fmaxf(s[j][2], s[j][3]));
        }
        rm0 = fmaxf(rm0, __shfl_xor_sync(0xffffffffu, rm0, 1));
        rm0 = fmaxf(rm0, __shfl_xor_sync(0xffffffffu, rm0, 2));
        rm1 = fmaxf(rm1, __shfl_xor_sync(0xffffffffu, rm1, 1));
        rm1 = fmaxf(rm1, __shfl_xor_sync(0xffffffffu, rm1, 2));
        float mN0 = fmaxf(m0, rm0), mN1 = fmaxf(m1, rm1);
        float fac0 = __expf(m0 - mN0), fac1 = __expf(m1 - mN1);
        m0 = mN0; m1 = mN1;
        float rs0 = 0.f, rs1 = 0.f;
        #pragma unroll
        for (int j=0;j<8;j++){
            s[j][0] = __expf(s[j][0] - mN0);
            s[j][1] = __expf(s[j][1] - mN0);
            s[j][2] = __expf(s[j][2] - mN1);
            s[j][3] = __expf(s[j][3] - mN1);
            rs0 += s[j][0] + s[j][1];
            rs1 += s[j][2] + s[j][3];
        }
        rs0 += __shfl_xor_sync(0xffffffffu, rs0, 1);
        rs0 += __shfl_xor_sync(0xffffffffu, rs0, 2);
        rs1 += __shfl_xor_sync(0xffffffffu, rs1, 1);
        rs1 += __shfl_xor_sync(0xffffffffu, rs1, 2);
        l0 = l0*fac0 + rs0;
        l1 = l1*fac1 + rs1;
        #pragma unroll
        for (int i=0;i<16;i++){
            o[i][0]*=fac0; o[i][1]*=fac0; o[i][2]*=fac1; o[i][3]*=fac1;
        }

        // ---- O += P V ----
        uint32_t vaBase = base + AT_V
            + ((uint32_t)(lane&7) + (((lane>>3)&1)<<3))*AT_ROWB
            + (((lane>>4)<<3)<<1);
        #pragma unroll
        for (int ks=0; ks<4; ks++){
            uint32_t aP[4];
            aP[0] = packh2(s[2*ks][0],   s[2*ks][1]);
            aP[1] = packh2(s[2*ks][2],   s[2*ks][3]);
            aP[2] = packh2(s[2*ks+1][0], s[2*ks+1][1]);
            aP[3] = packh2(s[2*ks+1][2], s[2*ks+1][3]);
            #pragma unroll
            for (int nt2=0; nt2<8; nt2++){
                uint32_t vf[4];
                ldsm4t(vf, vaBase + (uint32_t)ks*(16*AT_ROWB) + (uint32_t)nt2*32);
                mma_f16(o[2*nt2],   aP, vf[0], vf[1]);
                mma_f16(o[2*nt2+1], aP, vf[2], vf[3]);
            }
        }
    }

    // ---- epilogue: normalize + fp16 store ----
    float inv0 = 1.0f/l0, inv1 = 1.0f/l1;
    size_t r0off = (rowbase + (size_t)grow0)*Dn + colb + ((lane&3)<<1);
    size_t r1off = r0off + 8*(size_t)Dn;
    #pragma unroll
    for (int nt=0; nt<16; nt++){
        *(uint32_t*)&OgH[r0off + nt*8] = packh2(o[nt][0]*inv0, o[nt][1]*inv0);
        *(uint32_t*)&OgH[r1off + nt*8] = packh2(o[nt][2]*inv1, o[nt][3]*inv1);
    }
}

// ======================= launch =============================================
extern "C" void kernel_launch(void* const* d_in, const int* in_sizes, int n_in,
                              void* d_out, int out_size) {
    const float* x  = (const float*)d_in[0];
    const int*   tp = (const int*)d_in[2];
    const float* Wq = (const float*)d_in[3];
    const float* Wk = (const float*)d_in[4];
    const float* Wv = (const float*)d_in[5];
    const float* Wo = (const float*)d_in[6];
    float* out = (float*)d_out;

    float *Qp, *Kp, *Vp;
    __half *xH, *wH, *OH, *Qf, *Kf, *Vf;
    cudaGetSymbolAddress((void**)&Qp, g_Q);
    cudaGetSymbolAddress((void**)&Kp, g_K);
    cudaGetSymbolAddress((void**)&Vp, g_V);
    cudaGetSymbolAddress((void**)&xH, g_xH);
    cudaGetSymbolAddress((void**)&wH, g_wH);
    cudaGetSymbolAddress((void**)&OH, g_OH);
    cudaGetSymbolAddress((void**)&Qf, g_Qf);
    cudaGetSymbolAddress((void**)&Kf, g_Kf);
    cudaGetSymbolAddress((void**)&Vf, g_Vf);
    const size_t WS = (size_t)Dn*Dn;

    cudaFuncSetAttribute((const void*)gemm_fp16,
                         cudaFuncAttributeMaxDynamicSharedMemorySize, FG_SMEM);
    cudaFuncSetAttribute((const void*)attn_mma,
                         cudaFuncAttributeMaxDynamicSharedMemorySize, AT_SMEM);

    build_rope_tables<<<(MAXPOS*64 + 255)/256, 256>>>();

    // convert inputs to fp16
    const int n4x = MROWS*Dn/4, n4w = Dn*Dn/4;
    conv_f16<<<(n4x+255)/256, 256>>>(x,  xH,      n4x);
    conv_f16<<<(n4w+255)/256, 256>>>(Wq, wH+0*WS, n4w);
    conv_f16<<<(n4w+255)/256, 256>>>(Wk, wH+1*WS, n4w);
    conv_f16<<<(n4w+255)/256, 256>>>(Wv, wH+2*WS, n4w);
    conv_f16<<<(n4w+255)/256, 256>>>(Wo, wH+3*WS, n4w);

    // QKV projections (fp16 MMA, fp32 out)
    gemm_fp16<<<dim3(Dn/256, MROWS/128, 3), 256, FG_SMEM>>>(
        xH, wH+0*WS, wH+1*WS, wH+2*WS, Qp, Kp, Vp);

    // fused RoPE + fp16 convert of Q,K,V
    rope_conv<<<(Bn*Ln*Hn*64 + 255)/256, 256>>>(tp);

    attn_mma<<<dim3(Ln/128, Bn*Hn), 256, AT_SMEM>>>(Qf, Kf, Vf, OH);

    // output projection (fp16 MMA)
    gemm_fp16<<<dim3(Dn/256, MROWS/128, 1), 256, FG_SMEM>>>(
        OH, wH+3*WS, wH+3*WS, wH+3*WS, out, out, out);
}

// round 8
// speedup vs baseline: 8.1868x; 1.1616x over previous
#include <cuda_runtime.h>
#include <cuda_fp16.h>
#include <math.h>
#include <stdint.h>

#define Bn 2
#define Ln 2048
#define Dn 2048
#define Hn 16
#define DHn 128
#define MROWS (Bn*Ln)          // 4096
#define NQKV  (3*Dn)           // 6144
#define MAXPOS 4096

// ---------------- scratch (device globals; no allocation allowed) ----------
__device__ __half g_xH[(size_t)MROWS*Dn];
__device__ __half g_wH[4][(size_t)Dn*Dn];      // Wq,Wk,Wv contiguous; Wo last
__device__ __half g_QKVf[(size_t)MROWS*NQKV];  // fused Q|K|V fp16, post-RoPE
__device__ __half g_OH[(size_t)MROWS*Dn];
__device__ float g_cos[MAXPOS*64];
__device__ float g_sin[MAXPOS*64];

// ======================= helpers ============================================
__device__ __forceinline__ uint32_t smem_u32(const void* p){
    uint32_t a;
    asm("{ .reg .u64 t; cvta.to.shared.u64 t, %1; cvt.u32.u64 %0, t; }" : "=r"(a) : "l"(p));
    return a;
}
__device__ __forceinline__ void cp16(uint32_t s, const void* g){
    asm volatile("cp.async.cg.shared.global [%0], [%1], 16;" :: "r"(s), "l"(g));
}
__device__ __forceinline__ void ldsm4(uint32_t* r, uint32_t a){
    asm volatile("ldmatrix.sync.aligned.m8n8.x4.shared.b16 {%0,%1,%2,%3},[%4];"
        : "=r"(r[0]),"=r"(r[1]),"=r"(r[2]),"=r"(r[3]) : "r"(a));
}
__device__ __forceinline__ void ldsm4t(uint32_t* r, uint32_t a){
    asm volatile("ldmatrix.sync.aligned.m8n8.x4.trans.shared.b16 {%0,%1,%2,%3},[%4];"
        : "=r"(r[0]),"=r"(r[1]),"=r"(r[2]),"=r"(r[3]) : "r"(a));
}
__device__ __forceinline__ void mma_f16(float* c, const uint32_t* a, uint32_t b0, uint32_t b1){
    asm volatile("mma.sync.aligned.m16n8k16.row.col.f32.f16.f16.f32 "
        "{%0,%1,%2,%3},{%4,%5,%6,%7},{%8,%9},{%0,%1,%2,%3};"
        : "+f"(c[0]),"+f"(c[1]),"+f"(c[2]),"+f"(c[3])
        : "r"(a[0]),"r"(a[1]),"r"(a[2]),"r"(a[3]),"r"(b0),"r"(b1));
}
__device__ __forceinline__ uint32_t packh2(float x, float y){
    __half2 h = __floats2half2_rn(x, y);
    return *(uint32_t*)&h;
}

// ======================= RoPE tables ========================================
__global__ void build_rope_tables() {
    int idx = blockIdx.x * blockDim.x + threadIdx.x;
    if (idx >= MAXPOS*64) return;
    int pos = idx >> 6;
    int i   = idx & 63;
    float expo = (float)(2*i) * (1.0f/128.0f);
    float inv  = 1.0f / powf(10000.0f, expo);
    float ang  = (float)pos * inv;
    g_cos[idx] = cosf(ang);
    g_sin[idx] = sinf(ang);
}

// ======================= f32 -> fp16 conversion (all arrays, 1 launch) ======
// grid.y: 0..3 -> Wq,Wk,Wv,Wo ; 4,5 -> x halves
__global__ void conv_all(const float* __restrict__ x,
                         const float* __restrict__ Wq, const float* __restrict__ Wk,
                         const float* __restrict__ Wv, const float* __restrict__ Wo)
{
    const int n4w = Dn*Dn/4;
    int y = blockIdx.y;
    const float* src;
    __half* dst;
    if (y < 4){
        src = (y==0)?Wq:((y==1)?Wk:((y==2)?Wv:Wo));
        dst = &g_wH[y][0];
    } else {
        src = x  + (size_t)(y-4)*n4w*4;
        dst = g_xH + (size_t)(y-4)*n4w*4;
    }
    int i = blockIdx.x*blockDim.x + threadIdx.x;
    if (i >= n4w) return;
    float4 v = ((const float4*)src)[i];
    ((uint2*)dst)[i] = make_uint2(packh2(v.x,v.y), packh2(v.z,v.w));
}

// ======================= fused QKV GEMM + RoPE epilogue =====================
// C[m,n] = sum_k x[m,k]*Wqkv[n,k], M=4096, N=6144, K=2048.
// Tile 128x192, 8 warps (2x4), warp tile 64x48, BK=32, 3-stage cp.async.
// Epilogue: n<4096 (Q,K) -> RoPE rotate; all -> fp16 into g_QKVf[m][6144].
#define QSW     10240                 // A: 128 rows x 80 B
#define QSTAGE  25600                 // + W: 192 rows x 80 B
#define QG_SMEM (3*QSTAGE)            // 76800

__global__ __launch_bounds__(256)
void gemm_qkv(const __half* __restrict__ A, const __half* __restrict__ W,
              const int* __restrict__ tp, __half* __restrict__ Cf)
{
    extern __shared__ char smem[];
    uint32_t sb = smem_u32(smem);
    const int tid = threadIdx.x, wid = tid>>5, lane = tid&31;
    const int m0 = blockIdx.y*128, n0 = blockIdx.x*192;
    const int warp_m = (wid>>2)*64, warp_n = (wid&3)*48;

    auto load_stage = [&](int st, int kt){
        uint32_t sbase = sb + st*QSTAGE;
        #pragma unroll
        for (int j=0;j<5;j++){
            int c = tid + j*256;
            if (c < 512){
                int row = c>>2, seg = c&3;
                cp16(sbase + row*80 + seg*16,
                     A + (size_t)(m0+row)*Dn + kt*32 + seg*8);
            } else {
                int cc = c - 512; int row = cc>>2, seg = cc&3;
                cp16(sbase + QSW + row*80 + seg*16,
                     W + (size_t)(n0+row)*Dn + kt*32 + seg*8);
            }
        }
    };

    float acc[4][6][4];
    #pragma unroll
    for (int i=0;i<4;i++)
        #pragma unroll
        for (int j=0;j<6;j++)
            #pragma unroll
            for (int q=0;q<4;q++) acc[i][j][q]=0.f;

    load_stage(0, 0);
    asm volatile("cp.async.commit_group;");
    load_stage(1, 1);
    asm volatile("cp.async.commit_group;");

    const int lrow = lane & 15;
    const uint32_t lcolB = (uint32_t)((lane>>4)<<4);

    for (int kt=0; kt<64; ++kt){
        int st = kt - (kt/3)*3;
        uint32_t base = sb + st*QSTAGE;
        asm volatile("cp.async.wait_group 1;");
        __syncthreads();

        #pragma unroll
        for (int ks=0; ks<2; ++ks){
            uint32_t kB = ks*32;
            uint32_t aAddr = base + (uint32_t)(warp_m + lrow)*80 + lcolB + kB;
            uint32_t wAddr = base + QSW + (uint32_t)(warp_n + lrow)*80 + lcolB + kB;

            uint32_t ahr[4][4], whr[3][4];
            #pragma unroll
            for (int mt=0; mt<4; mt++) ldsm4(ahr[mt], aAddr + mt*(16*80));
            #pragma unroll
            for (int p=0; p<3; p++)   ldsm4(whr[p], wAddr + p*(16*80));
            #pragma unroll
            for (int mt=0; mt<4; mt++)
                #pragma unroll
                for (int p=0; p<3; p++){
                    mma_f16(acc[mt][2*p],   ahr[mt], whr[p][0], whr[p][2]);
                    mma_f16(acc[mt][2*p+1], ahr[mt], whr[p][1], whr[p][3]);
                }
        }

        if (kt+2 < 64){
            int st2 = (kt+2) - ((kt+2)/3)*3;
            load_stage(st2, kt+2);
        }
        asm volatile("cp.async.commit_group;");
        __syncthreads();
    }

    // ---- epilogue: RoPE (for Q,K cols) + fp16 store ----
    const int row0 = m0 + warp_m + (lane>>2);
    const int col0 = n0 + warp_n + ((lane&3)<<1);
    int pos[8];
    #pragma unroll
    for (int mt=0; mt<4; mt++){
        pos[2*mt]   = tp[row0 + mt*16];
        pos[2*mt+1] = tp[row0 + mt*16 + 8];
    }
    #pragma unroll
    for (int nt=0; nt<6; nt++){
        int col = col0 + nt*8;
        bool dorope = (col < 2*Dn);          // Q and K columns
        int ii = (col & 127) >> 1;
        #pragma unroll
        for (int mt=0; mt<4; mt++){
            float a0=acc[mt][nt][0], a1=acc[mt][nt][1];
            float a2=acc[mt][nt][2], a3=acc[mt][nt][3];
            uint32_t o0, o1;
            if (dorope){
                int p0 = pos[2*mt]*64 + ii, p1 = pos[2*mt+1]*64 + ii;
                float c0=g_cos[p0], s0=g_sin[p0];
                float c1=g_cos[p1], s1=g_sin[p1];
                o0 = packh2(a0*c0 - a1*s0, a0*s0 + a1*c0);
                o1 = packh2(a2*c1 - a3*s1, a2*s1 + a3*c1);
            } else {
                o0 = packh2(a0, a1);
                o1 = packh2(a2, a3);
            }
            *(uint32_t*)&Cf[(size_t)(row0 + mt*16)*NQKV + col]     = o0;
            *(uint32_t*)&Cf[(size_t)(row0 + mt*16 + 8)*NQKV + col] = o1;
        }
    }
}

// ======================= fp16 GEMM (output projection) ======================
// C[m,n] = sum_k A[m,k]*W[n,k], fp16 in, fp32 out. CTA 128x256, BK=32.
#define FSW     10240
#define FSTAGE  30720
#define FG_SMEM (3*FSTAGE)   // 92160

__global__ __launch_bounds__(256)
void gemm_fp16(const __half* __restrict__ A, const __half* __restrict__ W,
               float* __restrict__ C)
{
    extern __shared__ char smem[];
    uint32_t sb = smem_u32(smem);
    const int tid = threadIdx.x, wid = tid>>5, lane = tid&31;
    const int m0 = blockIdx.y*128, n0 = blockIdx.x*256;
    const int warp_m = (wid>>2)*64, warp_n = (wid&3)*64;

    auto load_stage = [&](int st, int kt){
        uint32_t sbase = sb + st*FSTAGE;
        #pragma unroll
        for (int j=0;j<6;j++){
            int c = tid + j*256;
            if (c < 512){
                int row = c>>2, seg = c&3;
                cp16(sbase + row*80 + seg*16,
                     A + (size_t)(m0+row)*Dn + kt*32 + seg*8);
            } else {
                int cc = c - 512; int row = cc>>2, seg = cc&3;
                cp16(sbase + FSW + row*80 + seg*16,
                     W + (size_t)(n0+row)*Dn + kt*32 + seg*8);
            }
        }
    };

    float acc[4][8][4];
    #pragma unroll
    for (int i=0;i<4;i++)
        #pragma unroll
        for (int j=0;j<8;j++)
            #pragma unroll
            for (int q=0;q<4;q++) acc[i][j][q]=0.f;

    load_stage(0, 0);
    asm volatile("cp.async.commit_group;");
    load_stage(1, 1);
    asm volatile("cp.async.commit_group;");

    const int lrow = lane & 15;
    const uint32_t lcolB = (uint32_t)((lane>>4)<<4);

    for (int kt=0; kt<64; ++kt){
        int st = kt - (kt/3)*3;
        uint32_t base = sb + st*FSTAGE;
        asm volatile("cp.async.wait_group 1;");
        __syncthreads();

        #pragma unroll
        for (int ks=0; ks<2; ++ks){
            uint32_t kB = ks*32;
            uint32_t aAddr = base + (uint32_t)(warp_m + lrow)*80 + lcolB + kB;
            uint32_t wAddr = base + FSW + (uint32_t)(warp_n + lrow)*80 + lcolB + kB;

            uint32_t ahr[4][4], whr[4][4];
            #pragma unroll
            for (int mt=0; mt<4; mt++) ldsm4(ahr[mt], aAddr + mt*(16*80));
            #pragma unroll
            for (int p=0; p<4; p++)   ldsm4(whr[p], wAddr + p*(16*80));
            #pragma unroll
            for (int mt=0; mt<4; mt++)
                #pragma unroll
                for (int p=0; p<4; p++){
                    mma_f16(acc[mt][2*p],   ahr[mt], whr[p][0], whr[p][2]);
                    mma_f16(acc[mt][2*p+1], ahr[mt], whr[p][1], whr[p][3]);
                }
        }

        if (kt+2 < 64){
            int st2 = (kt+2) - ((kt+2)/3)*3;
            load_stage(st2, kt+2);
        }
        asm volatile("cp.async.commit_group;");
        __syncthreads();
    }

    const int row0 = m0 + warp_m + (lane>>2);
    const int col0 = n0 + warp_n + ((lane&3)<<1);
    #pragma unroll
    for (int mt=0; mt<4; mt++){
        #pragma unroll
        for (int nt=0; nt<8; nt++){
            float* p0 = C + (size_t)(row0 + mt*16)*Dn + col0 + nt*8;
            float* p1 = p0 + 8*(size_t)Dn;
            *(float2*)p0 = make_float2(acc[mt][nt][0], acc[mt][nt][1]);
            *(float2*)p1 = make_float2(acc[mt][nt][2], acc[mt][nt][3]);
        }
    }
}

// ======================= fp16 tensor-core flash attention ===================
// Q/K/V read from fused g_QKVf [4096][6144]: Q cols 0.., K +2048, V +4096.
// CTA: 128 q-rows x one head. 8 warps. K/V tiles 64 rows, 2-stage cp.async.
#define QLD 6144
#define AT_ROWB 272
#define AT_K    0
#define AT_V    17408
#define AT_STAGE 34816
#define AT_QOFF (2*AT_STAGE)
#define AT_SMEM (2*AT_STAGE + 34816)         // 104448

__global__ __launch_bounds__(256, 1)
void attn_mma(const __half* __restrict__ QKV, __half* __restrict__ OgH)
{
    extern __shared__ char sm[];
    uint32_t sb = smem_u32(sm);
    const int tid = threadIdx.x, w = tid>>5, lane = tid&31;
    const int qb = (int)(gridDim.x - 1 - blockIdx.x);     // heavy tiles first
    const int bh = blockIdx.y;
    const int b = bh>>4, h = bh&15;
    const size_t rowbase = (size_t)b*Ln;
    const size_t colb = (size_t)h*128;
    const int kmax = 2*qb + 1;

    {   // Q: 2048 16B chunks (128 rows x 256 B)
        #pragma unroll
        for (int j=0;j<8;j++){
            int c = tid + j*256;
            int r = c>>4, seg = c&15;
            const char* src = (const char*)QKV
                + (((rowbase + (size_t)qb*128 + r)*QLD + colb)<<1) + seg*16;
            cp16(sb + AT_QOFF + r*AT_ROWB + seg*16, src);
        }
        asm volatile("cp.async.commit_group;");
    }
    auto issue_kv = [&](int kb2, int st){
        uint32_t sbase = sb + st*AT_STAGE;
        #pragma unroll
        for (int j=0;j<8;j++){
            int c = tid + j*256;
            int arr = c>>10, r = (c>>4)&63, seg = c&15;
            size_t coff = colb + (size_t)(arr ? 2*Dn : Dn);   // K at +2048, V at +4096
            const char* src = (const char*)QKV
                + (((rowbase + (size_t)kb2*64 + r)*QLD + coff)<<1) + seg*16;
            cp16(sbase + arr*17408 + r*AT_ROWB + seg*16, src);
        }
    };
    issue_kv(0, 0);
    asm volatile("cp.async.commit_group;");

    asm volatile("cp.async.wait_group 1;");
    __syncthreads();
    uint32_t qf[8][4];
    {
        uint32_t qa = sb + AT_QOFF + (uint32_t)(w*16 + (lane&15))*AT_ROWB + ((lane>>4)<<4);
        #pragma unroll
        for (int ks=0; ks<8; ks++) ldsm4(qf[ks], qa + ks*32);
    }

    float o[16][4];
    #pragma unroll
    for (int i=0;i<16;i++){ o[i][0]=0.f;o[i][1]=0.f;o[i][2]=0.f;o[i][3]=0.f; }
    float m0 = -1e30f, m1 = -1e30f, l0 = 0.f, l1 = 0.f;
    const float scale = 0.08838834764831845f;
    const int grow0 = qb*128 + w*16 + (lane>>2);

    for (int kb=0; kb<=kmax; ++kb){
        __syncthreads();
        if (kb+1 <= kmax) issue_kv(kb+1, (kb+1)&1);
        asm volatile("cp.async.commit_group;");
        asm volatile("cp.async.wait_group 1;");
        __syncthreads();
        uint32_t base = sb + (uint32_t)(kb&1)*AT_STAGE;

        // ---- S = Q K^T ----
        float s[8][4];
        #pragma unroll
        for (int j=0;j<8;j++){ s[j][0]=0.f;s[j][1]=0.f;s[j][2]=0.f;s[j][3]=0.f; }
        uint32_t kaBase = base + AT_K + (uint32_t)(lane&15)*AT_ROWB + ((lane>>4)<<4);
        #pragma unroll
        for (int ks=0; ks<8; ks++){
            #pragma unroll
            for (int p2=0; p2<4; p2++){
                uint32_t kf[4];
                ldsm4(kf, kaBase + (uint32_t)p2*(16*AT_ROWB) + ks*32);
                mma_f16(s[2*p2],   qf[ks], kf[0], kf[2]);
                mma_f16(s[2*p2+1], qf[ks], kf[1], kf[3]);
            }
        }

        // ---- scale + causal mask ----
        if (kb >= 2*qb){
            #pragma unroll
            for (int j=0;j<8;j++){
                int gc = kb*64 + j*8 + ((lane&3)<<1);
                s[j][0] = (gc   <= grow0)   ? s[j][0]*scale : -1e30f;
                s[j][1] = (gc+1 <= grow0)   ? s[j][1]*scale : -1e30f;
                s[j][2] = (gc   <= grow0+8) ? s[j][2]*scale : -1e30f;
                s[j][3] = (gc+1 <= grow0+8) ? s[j][3]*scale : -1e30f;
            }
        } else {
            #pragma unroll
            for (int j=0;j<8;j++){
                s[j][0]*=scale; s[j][1]*=scale; s[j][2]*=scale; s[j][3]*=scale;
            }
        }

        // ---- online softmax ----
        float rm0 = -1e30f, rm1 = -1e30f;
        #pragma unroll
        for (int j=0;j<8;j++){
            rm0 = fmaxf(rm0, fmaxf(s[j][0], s[j][1]));
            rm1 = fmaxf(rm1, fmaxf(s[j][2], s[j][3]));
        }
        rm0 = fmaxf(rm0, __shfl_xor_sync(0xffffffffu, rm0, 1));
        rm0 = fmaxf(rm0, __shfl_xor_sync(0xffffffffu, rm0, 2));
        rm1 = fmaxf(rm1, __shfl_xor_sync(0xffffffffu, rm1, 1));
        rm1 = fmaxf(rm1, __shfl_xor_sync(0xffffffffu, rm1, 2));
        float mN0 = fmaxf(m0, rm0), mN1 = fmaxf(m1, rm1);
        float fac0 = __expf(m0 - mN0), fac1 = __expf(m1 - mN1);
        m0 = mN0; m1 = mN1;
        float rs0 = 0.f, rs1 = 0.f;
        #pragma unroll
        for (int j=0;j<8;j++){
            s[j][0] = __expf(s[j][0] - mN0);
            s[j][1] = __expf(s[j][1] - mN0);
            s[j][2] = __expf(s[j][2] - mN1);
            s[j][3] = __expf(s[j][3] - mN1);
            rs0 += s[j][0] + s[j][1];
            rs1 += s[j][2] + s[j][3];
        }
        rs0 += __shfl_xor_sync(0xffffffffu, rs0, 1);
        rs0 += __shfl_xor_sync(0xffffffffu, rs0, 2);
        rs1 += __shfl_xor_sync(0xffffffffu, rs1, 1);
        rs1 += __shfl_xor_sync(0xffffffffu, rs1, 2);
        l0 = l0*fac0 + rs0;
        l1 = l1*fac1 + rs1;
        #pragma unroll
        for (int i=0;i<16;i++){
            o[i][0]*=fac0; o[i][1]*=fac0; o[i][2]*=fac1; o[i][3]*=fac1;
        }

        // ---- O += P V ----
        uint32_t vaBase = base + AT_V
            + ((uint32_t)(lane&7) + (((lane>>3)&1)<<3))*AT_ROWB
            + (((lane>>4)<<3)<<1);
        #pragma unroll
        for (int ks=0; ks<4; ks++){
            uint32_t aP[4];
            aP[0] = packh2(s[2*ks][0],   s[2*ks][1]);
            aP[1] = packh2(s[2*ks][2],   s[2*ks][3]);
            aP[2] = packh2(s[2*ks+1][0], s[2*ks+1][1]);
            aP[3] = packh2(s[2*ks+1][2], s[2*ks+1][3]);
            #pragma unroll
            for (int nt2=0; nt2<8; nt2++){
                uint32_t vf[4];
                ldsm4t(vf, vaBase + (uint32_t)ks*(16*AT_ROWB) + (uint32_t)nt2*32);
                mma_f16(o[2*nt2],   aP, vf[0], vf[1]);
                mma_f16(o[2*nt2+1], aP, vf[2], vf[3]);
            }
        }
    }

    // ---- epilogue: normalize + fp16 store (stride Dn for Wo GEMM) ----
    float inv0 = 1.0f/l0, inv1 = 1.0f/l1;
    size_t r0off = (rowbase + (size_t)grow0)*Dn + colb + ((lane&3)<<1);
    size_t r1off = r0off + 8*(size_t)Dn;
    #pragma unroll
    for (int nt=0; nt<16; nt++){
        *(uint32_t*)&OgH[r0off + nt*8] = packh2(o[nt][0]*inv0, o[nt][1]*inv0);
        *(uint32_t*)&OgH[r1off + nt*8] = packh2(o[nt][2]*inv1, o[nt][3]*inv1);
    }
}

// ======================= launch =============================================
extern "C" void kernel_launch(void* const* d_in, const int* in_sizes, int n_in,
                              void* d_out, int out_size) {
    const float* x  = (const float*)d_in[0];
    const int*   tp = (const int*)d_in[2];
    const float* Wq = (const float*)d_in[3];
    const float* Wk = (const float*)d_in[4];
    const float* Wv = (const float*)d_in[5];
    const float* Wo = (const float*)d_in[6];
    float* out = (float*)d_out;

    __half *xH, *wH, *OH, *QKVf;
    cudaGetSymbolAddress((void**)&xH, g_xH);
    cudaGetSymbolAddress((void**)&wH, g_wH);
    cudaGetSymbolAddress((void**)&OH, g_OH);
    cudaGetSymbolAddress((void**)&QKVf, g_QKVf);
    const size_t WS = (size_t)Dn*Dn;

    cudaFuncSetAttribute((const void*)gemm_qkv,
                         cudaFuncAttributeMaxDynamicSharedMemorySize, QG_SMEM);
    cudaFuncSetAttribute((const void*)gemm_fp16,
                         cudaFuncAttributeMaxDynamicSharedMemorySize, FG_SMEM);
    cudaFuncSetAttribute((const void*)attn_mma,
                         cudaFuncAttributeMaxDynamicSharedMemorySize, AT_SMEM);

    build_rope_tables<<<(MAXPOS*64 + 255)/256, 256>>>();

    // fp16 conversion of x and all weights, one launch
    conv_all<<<dim3((Dn*Dn/4 + 255)/256, 6), 256>>>(x, Wq, Wk, Wv, Wo);

    // fused QKV projection + RoPE + fp16 (N=6144, tile 128x192 -> 1024 CTAs)
    gemm_qkv<<<dim3(NQKV/192, MROWS/128), 256, QG_SMEM>>>(xH, wH, tp, QKVf);

    // flash attention (fp16 MMA)
    attn_mma<<<dim3(Ln/128, Bn*Hn), 256, AT_SMEM>>>(QKVf, OH);

    // output projection
    gemm_fp16<<<dim3(Dn/256, MROWS/128), 256, FG_SMEM>>>(OH, wH+3*WS, out);
}

// round 9
// speedup vs baseline: 8.4666x; 1.0342x over previous
#include <cuda_runtime.h>
#include <cuda_fp16.h>
#include <math.h>
#include <stdint.h>

#define Bn 2
#define Ln 2048
#define Dn 2048
#define Hn 16
#define DHn 128
#define MROWS (Bn*Ln)          // 4096
#define NQKV  (3*Dn)           // 6144
#define MAXPOS 4096

// ---------------- scratch (device globals; no allocation allowed) ----------
__device__ __half g_xH[(size_t)MROWS*Dn];
__device__ __half g_wH[4][(size_t)Dn*Dn];      // Wq,Wk,Wv contiguous; Wo last
__device__ __half g_QKVf[(size_t)MROWS*NQKV];  // fused Q|K|V fp16, post-RoPE
__device__ __half g_OH[(size_t)MROWS*Dn];
__device__ float g_cos[MAXPOS*64];
__device__ float g_sin[MAXPOS*64];

// ======================= helpers ============================================
__device__ __forceinline__ uint32_t smem_u32(const void* p){
    uint32_t a;
    asm("{ .reg .u64 t; cvta.to.shared.u64 t, %1; cvt.u32.u64 %0, t; }" : "=r"(a) : "l"(p));
    return a;
}
__device__ __forceinline__ void cp16(uint32_t s, const void* g){
    asm volatile("cp.async.cg.shared.global [%0], [%1], 16;" :: "r"(s), "l"(g));
}
__device__ __forceinline__ void ldsm4(uint32_t* r, uint32_t a){
    asm volatile("ldmatrix.sync.aligned.m8n8.x4.shared.b16 {%0,%1,%2,%3},[%4];"
        : "=r"(r[0]),"=r"(r[1]),"=r"(r[2]),"=r"(r[3]) : "r"(a));
}
__device__ __forceinline__ void ldsm4t(uint32_t* r, uint32_t a){
    asm volatile("ldmatrix.sync.aligned.m8n8.x4.trans.shared.b16 {%0,%1,%2,%3},[%4];"
        : "=r"(r[0]),"=r"(r[1]),"=r"(r[2]),"=r"(r[3]) : "r"(a));
}
__device__ __forceinline__ void mma_f16(float* c, const uint32_t* a, uint32_t b0, uint32_t b1){
    asm volatile("mma.sync.aligned.m16n8k16.row.col.f32.f16.f16.f32 "
        "{%0,%1,%2,%3},{%4,%5,%6,%7},{%8,%9},{%0,%1,%2,%3};"
        : "+f"(c[0]),"+f"(c[1]),"+f"(c[2]),"+f"(c[3])
        : "r"(a[0]),"r"(a[1]),"r"(a[2]),"r"(a[3]),"r"(b0),"r"(b1));
}
__device__ __forceinline__ uint32_t packh2(float x, float y){
    __half2 h = __floats2half2_rn(x, y);
    return *(uint32_t*)&h;
}
__device__ __forceinline__ float ex2(float x){
    float r;
    asm("ex2.approx.f32 %0, %1;" : "=f"(r) : "f"(x));
    return r;
}

// ======================= conversion + RoPE tables (1 launch) ================
// grid.y: 0..3 -> Wq,Wk,Wv,Wo ; 4,5 -> x halves ; 6 -> rope tables
__global__ void conv_all(const float* __restrict__ x,
                         const float* __restrict__ Wq, const float* __restrict__ Wk,
                         const float* __restrict__ Wv, const float* __restrict__ Wo)
{
    const int n4w = Dn*Dn/4;
    int y = blockIdx.y;
    if (y == 6){
        int idx = blockIdx.x*blockDim.x + threadIdx.x;
        if (idx >= MAXPOS*64) return;
        int pos = idx >> 6;
        int i   = idx & 63;
        float expo = (float)(2*i) * (1.0f/128.0f);
        float inv  = 1.0f / powf(10000.0f, expo);
        float ang  = (float)pos * inv;
        g_cos[idx] = cosf(ang);
        g_sin[idx] = sinf(ang);
        return;
    }
    const float* src;
    __half* dst;
    if (y < 4){
        src = (y==0)?Wq:((y==1)?Wk:((y==2)?Wv:Wo));
        dst = &g_wH[y][0];
    } else {
        src = x  + (size_t)(y-4)*n4w*4;
        dst = g_xH + (size_t)(y-4)*n4w*4;
    }
    int i = blockIdx.x*blockDim.x + threadIdx.x;
    if (i >= n4w) return;
    float4 v = ((const float4*)src)[i];
    ((uint2*)dst)[i] = make_uint2(packh2(v.x,v.y), packh2(v.z,v.w));
}

// ======================= fused QKV GEMM + RoPE epilogue =====================
// C[m,n] = sum_k x[m,k]*Wqkv[n,k], M=4096, N=6144, K=2048.
// Tile 128x192, 8 warps (2x4), warp tile 64x48, BK=32, 3-stage cp.async.
#define QSW     10240
#define QSTAGE  25600
#define QG_SMEM (3*QSTAGE)            // 76800

__global__ __launch_bounds__(256)
void gemm_qkv(const __half* __restrict__ A, const __half* __restrict__ W,
              const int* __restrict__ tp, __half* __restrict__ Cf)
{
    extern __shared__ char smem[];
    uint32_t sb = smem_u32(smem);
    const int tid = threadIdx.x, wid = tid>>5, lane = tid&31;
    const int m0 = blockIdx.y*128, n0 = blockIdx.x*192;
    const int warp_m = (wid>>2)*64, warp_n = (wid&3)*48;

    auto load_stage = [&](int st, int kt){
        uint32_t sbase = sb + st*QSTAGE;
        #pragma unroll
        for (int j=0;j<5;j++){
            int c = tid + j*256;
            if (c < 512){
                int row = c>>2, seg = c&3;
                cp16(sbase + row*80 + seg*16,
                     A + (size_t)(m0+row)*Dn + kt*32 + seg*8);
            } else {
                int cc = c - 512; int row = cc>>2, seg = cc&3;
                cp16(sbase + QSW + row*80 + seg*16,
                     W + (size_t)(n0+row)*Dn + kt*32 + seg*8);
            }
        }
    };

    float acc[4][6][4];
    #pragma unroll
    for (int i=0;i<4;i++)
        #pragma unroll
        for (int j=0;j<6;j++)
            #pragma unroll
            for (int q=0;q<4;q++) acc[i][j][q]=0.f;

    load_stage(0, 0);
    asm volatile("cp.async.commit_group;");
    load_stage(1, 1);
    asm volatile("cp.async.commit_group;");

    const int lrow = lane & 15;
    const uint32_t lcolB = (uint32_t)((lane>>4)<<4);

    for (int kt=0; kt<64; ++kt){
        int st = kt - (kt/3)*3;
        uint32_t base = sb + st*QSTAGE;
        asm volatile("cp.async.wait_group 1;");
        __syncthreads();

        #pragma unroll
        for (int ks=0; ks<2; ++ks){
            uint32_t kB = ks*32;
            uint32_t aAddr = base + (uint32_t)(warp_m + lrow)*80 + lcolB + kB;
            uint32_t wAddr = base + QSW + (uint32_t)(warp_n + lrow)*80 + lcolB + kB;

            uint32_t ahr[4][4], whr[3][4];
            #pragma unroll
            for (int mt=0; mt<4; mt++) ldsm4(ahr[mt], aAddr + mt*(16*80));
            #pragma unroll
            for (int p=0; p<3; p++)   ldsm4(whr[p], wAddr + p*(16*80));
            #pragma unroll
            for (int mt=0; mt<4; mt++)
                #pragma unroll
                for (int p=0; p<3; p++){
                    mma_f16(acc[mt][2*p],   ahr[mt], whr[p][0], whr[p][2]);
                    mma_f16(acc[mt][2*p+1], ahr[mt], whr[p][1], whr[p][3]);
                }
        }

        if (kt+2 < 64){
            int st2 = (kt+2) - ((kt+2)/3)*3;
            load_stage(st2, kt+2);
        }
        asm volatile("cp.async.commit_group;");
        __syncthreads();
    }

    // ---- epilogue: RoPE (Q,K cols) + fp16 store ----
    const int row0 = m0 + warp_m + (lane>>2);
    const int col0 = n0 + warp_n + ((lane&3)<<1);
    int pos[8];
    #pragma unroll
    for (int mt=0; mt<4; mt++){
        pos[2*mt]   = tp[row0 + mt*16];
        pos[2*mt+1] = tp[row0 + mt*16 + 8];
    }
    #pragma unroll
    for (int nt=0; nt<6; nt++){
        int col = col0 + nt*8;
        bool dorope = (col < 2*Dn);
        int ii = (col & 127) >> 1;
        #pragma unroll
        for (int mt=0; mt<4; mt++){
            float a0=acc[mt][nt][0], a1=acc[mt][nt][1];
            float a2=acc[mt][nt][2], a3=acc[mt][nt][3];
            uint32_t o0, o1;
            if (dorope){
                int p0 = pos[2*mt]*64 + ii, p1 = pos[2*mt+1]*64 + ii;
                float c0=g_cos[p0], s0=g_sin[p0];
                float c1=g_cos[p1], s1=g_sin[p1];
                o0 = packh2(a0*c0 - a1*s0, a0*s0 + a1*c0);
                o1 = packh2(a2*c1 - a3*s1, a2*s1 + a3*c1);
            } else {
                o0 = packh2(a0, a1);
                o1 = packh2(a2, a3);
            }
            *(uint32_t*)&Cf[(size_t)(row0 + mt*16)*NQKV + col]     = o0;
            *(uint32_t*)&Cf[(size_t)(row0 + mt*16 + 8)*NQKV + col] = o1;
        }
    }
}

// ======================= fp16 GEMM (output projection) ======================
#define FSW     10240
#define FSTAGE  30720
#define FG_SMEM (3*FSTAGE)   // 92160

__global__ __launch_bounds__(256)
void gemm_fp16(const __half* __restrict__ A, const __half* __restrict__ W,
               float* __restrict__ C)
{
    extern __shared__ char smem[];
    uint32_t sb = smem_u32(smem);
    const int tid = threadIdx.x, wid = tid>>5, lane = tid&31;
    const int m0 = blockIdx.y*128, n0 = blockIdx.x*256;
    const int warp_m = (wid>>2)*64, warp_n = (wid&3)*64;

    auto load_stage = [&](int st, int kt){
        uint32_t sbase = sb + st*FSTAGE;
        #pragma unroll
        for (int j=0;j<6;j++){
            int c = tid + j*256;
            if (c < 512){
                int row = c>>2, seg = c&3;
                cp16(sbase + row*80 + seg*16,
                     A + (size_t)(m0+row)*Dn + kt*32 + seg*8);
            } else {
                int cc = c - 512; int row = cc>>2, seg = cc&3;
                cp16(sbase + FSW + row*80 + seg*16,
                     W + (size_t)(n0+row)*Dn + kt*32 + seg*8);
            }
        }
    };

    float acc[4][8][4];
    #pragma unroll
    for (int i=0;i<4;i++)
        #pragma unroll
        for (int j=0;j<8;j++)
            #pragma unroll
            for (int q=0;q<4;q++) acc[i][j][q]=0.f;

    load_stage(0, 0);
    asm volatile("cp.async.commit_group;");
    load_stage(1, 1);
    asm volatile("cp.async.commit_group;");

    const int lrow = lane & 15;
    const uint32_t lcolB = (uint32_t)((lane>>4)<<4);

    for (int kt=0; kt<64; ++kt){
        int st = kt - (kt/3)*3;
        uint32_t base = sb + st*FSTAGE;
        asm volatile("cp.async.wait_group 1;");
        __syncthreads();

        #pragma unroll
        for (int ks=0; ks<2; ++ks){
            uint32_t kB = ks*32;
            uint32_t aAddr = base + (uint32_t)(warp_m + lrow)*80 + lcolB + kB;
            uint32_t wAddr = base + FSW + (uint32_t)(warp_n + lrow)*80 + lcolB + kB;

            uint32_t ahr[4][4], whr[4][4];
            #pragma unroll
            for (int mt=0; mt<4; mt++) ldsm4(ahr[mt], aAddr + mt*(16*80));
            #pragma unroll
            for (int p=0; p<4; p++)   ldsm4(whr[p], wAddr + p*(16*80));
            #pragma unroll
            for (int mt=0; mt<4; mt++)
                #pragma unroll
                for (int p=0; p<4; p++){
                    mma_f16(acc[mt][2*p],   ahr[mt], whr[p][0], whr[p][2]);
                    mma_f16(acc[mt][2*p+1], ahr[mt], whr[p][1], whr[p][3]);
                }
        }

        if (kt+2 < 64){
            int st2 = (kt+2) - ((kt+2)/3)*3;
            load_stage(st2, kt+2);
        }
        asm volatile("cp.async.commit_group;");
        __syncthreads();
    }

    const int row0 = m0 + warp_m + (lane>>2);
    const int col0 = n0 + warp_n + ((lane&3)<<1);
    #pragma unroll
    for (int mt=0; mt<4; mt++){
        #pragma unroll
        for (int nt=0; nt<8; nt++){
            float* p0 = C + (size_t)(row0 + mt*16)*Dn + col0 + nt*8;
            float* p1 = p0 + 8*(size_t)Dn;
            *(float2*)p0 = make_float2(acc[mt][nt][0], acc[mt][nt][1]);
            *(float2*)p1 = make_float2(acc[mt][nt][2], acc[mt][nt][3]);
        }
    }
}

// ======================= fp16 tensor-core flash attention ===================
// Q/K/V from fused g_QKVf [4096][6144]. CTA: 128 q-rows x one head, 8 warps.
// KV tiles 128 rows, 2-stage cp.async. Base-2 online softmax.
#define QLD 6144
#define AT_ROWB 272
#define AT_K    0
#define AT_V    34816                        // 128 rows x 272 B
#define AT_STAGE 69632
#define AT_QOFF (2*AT_STAGE)                 // 139264
#define AT_SMEM (2*AT_STAGE + 34816)         // 174080

__global__ __launch_bounds__(256, 1)
void attn_mma(const __half* __restrict__ QKV, __half* __restrict__ OgH)
{
    extern __shared__ char sm[];
    uint32_t sb = smem_u32(sm);
    const int tid = threadIdx.x, w = tid>>5, lane = tid&31;
    const int qb = (int)(gridDim.x - 1 - blockIdx.x);     // heavy tiles first
    const int bh = blockIdx.y;
    const int b = bh>>4, h = bh&15;
    const size_t rowbase = (size_t)b*Ln;
    const size_t colb = (size_t)h*128;

    {   // Q: 128 rows x 256 B
        #pragma unroll
        for (int j=0;j<8;j++){
            int c = tid + j*256;
            int r = c>>4, seg = c&15;
            const char* src = (const char*)QKV
                + (((rowbase + (size_t)qb*128 + r)*QLD + colb)<<1) + seg*16;
            cp16(sb + AT_QOFF + r*AT_ROWB + seg*16, src);
        }
        asm volatile("cp.async.commit_group;");
    }
    auto issue_kv = [&](int kb2, int st){
        uint32_t sbase = sb + st*AT_STAGE;
        #pragma unroll
        for (int j=0;j<16;j++){
            int c = tid + j*256;
            int arr = c>>11, r = (c>>4)&127, seg = c&15;
            size_t coff = colb + (size_t)((1+arr)*Dn);    // K at +2048, V at +4096
            const char* src = (const char*)QKV
                + (((rowbase + (size_t)kb2*128 + r)*QLD + coff)<<1) + seg*16;
            cp16(sbase + arr*AT_V + r*AT_ROWB + seg*16, src);
        }
    };
    issue_kv(0, 0);
    asm volatile("cp.async.commit_group;");

    asm volatile("cp.async.wait_group 1;");
    __syncthreads();
    uint32_t qf[8][4];
    {
        uint32_t qa = sb + AT_QOFF + (uint32_t)(w*16 + (lane&15))*AT_ROWB + ((lane>>4)<<4);
        #pragma unroll
        for (int ks=0; ks<8; ks++) ldsm4(qf[ks], qa + ks*32);
    }

    float o[16][4];
    #pragma unroll
    for (int i=0;i<16;i++){ o[i][0]=0.f;o[i][1]=0.f;o[i][2]=0.f;o[i][3]=0.f; }
    float m0 = -1e30f, m1 = -1e30f, l0 = 0.f, l1 = 0.f;
    // 1/sqrt(128) * log2(e): base-2 softmax
    const float scale2 = 0.12753785166876984f;
    const int grow0 = qb*128 + w*16 + (lane>>2);

    for (int kb=0; kb<=qb; ++kb){
        __syncthreads();
        if (kb+1 <= qb) issue_kv(kb+1, (kb+1)&1);
        asm volatile("cp.async.commit_group;");
        asm volatile("cp.async.wait_group 1;");
        __syncthreads();
        uint32_t base = sb + (uint32_t)(kb&1)*AT_STAGE;

        // ---- S = Q K^T (128 cols) ----
        float s[16][4];
        #pragma unroll
        for (int j=0;j<16;j++){ s[j][0]=0.f;s[j][1]=0.f;s[j][2]=0.f;s[j][3]=0.f; }
        uint32_t kaBase = base + AT_K + (uint32_t)(lane&15)*AT_ROWB + ((lane>>4)<<4);
        #pragma unroll
        for (int ks=0; ks<8; ks++){
            #pragma unroll
            for (int p2=0; p2<8; p2++){
                uint32_t kf[4];
                ldsm4(kf, kaBase + (uint32_t)p2*(16*AT_ROWB) + ks*32);
                mma_f16(s[2*p2],   qf[ks], kf[0], kf[2]);
                mma_f16(s[2*p2+1], qf[ks], kf[1], kf[3]);
            }
        }

        // ---- scale (log2 units) + causal mask ----
        if (kb == qb){
            #pragma unroll
            for (int j=0;j<16;j++){
                int gc = kb*128 + j*8 + ((lane&3)<<1);
                s[j][0] = (gc   <= grow0)   ? s[j][0]*scale2 : -1e30f;
                s[j][1] = (gc+1 <= grow0)   ? s[j][1]*scale2 : -1e30f;
                s[j][2] = (gc   <= grow0+8) ? s[j][2]*scale2 : -1e30f;
                s[j][3] = (gc+1 <= grow0+8) ? s[j][3]*scale2 : -1e30f;
            }
        } else {
            #pragma unroll
            for (int j=0;j<16;j++){
                s[j][0]*=scale2; s[j][1]*=scale2; s[j][2]*=scale2; s[j][3]*=scale2;
            }
        }

        // ---- base-2 online softmax ----
        float rm0 = -1e30f, rm1 = -1e30f;
        #pragma unroll
        for (int j=0;j<16;j++){
            rm0 = fmaxf(rm0, fmaxf(s[j][0], s[j][1]));
            rm1 = fmaxf(rm1, fmaxf(s[j][2], s[j][3]));
        }
        rm0 = fmaxf(rm0, __shfl_xor_sync(0xffffffffu, rm0, 1));
        rm0 = fmaxf(rm0, __shfl_xor_sync(0xffffffffu, rm0, 2));
        rm1 = fmaxf(rm1, __shfl_xor_sync(0xffffffffu, rm1, 1));
        rm1 = fmaxf(rm1, __shfl_xor_sync(0xffffffffu, rm1, 2));
        float mN0 = fmaxf(m0, rm0), mN1 = fmaxf(m1, rm1);
        float fac0 = ex2(m0 - mN0), fac1 = ex2(m1 - mN1);
        m0 = mN0; m1 = mN1;
        float rs0 = 0.f, rs1 = 0.f;
        #pragma unroll
        for (int j=0;j<16;j++){
            s[j][0] = ex2(s[j][0] - mN0);
            s[j][1] = ex2(s[j][1] - mN0);
            s[j][2] = ex2(s[j][2] - mN1);
            s[j][3] = ex2(s[j][3] - mN1);
            rs0 += s[j][0] + s[j][1];
            rs1 += s[j][2] + s[j][3];
        }
        rs0 += __shfl_xor_sync(0xffffffffu, rs0, 1);
        rs0 += __shfl_xor_sync(0xffffffffu, rs0, 2);
        rs1 += __shfl_xor_sync(0xffffffffu, rs1, 1);
        rs1 += __shfl_xor_sync(0xffffffffu, rs1, 2);
        l0 = l0*fac0 + rs0;
        l1 = l1*fac1 + rs1;
        #pragma unroll
        for (int i=0;i<16;i++){
            o[i][0]*=fac0; o[i][1]*=fac0; o[i][2]*=fac1; o[i][3]*=fac1;
        }

        // ---- O += P V (K dim = 128) ----
        uint32_t vaBase = base + AT_V
            + ((uint32_t)(lane&7) + (((lane>>3)&1)<<3))*AT_ROWB
            + (((lane>>4)<<3)<<1);
        #pragma unroll
        for (int ks=0; ks<8; ks++){
            uint32_t aP[4];
            aP[0] = packh2(s[2*ks][0],   s[2*ks][1]);
            aP[1] = packh2(s[2*ks][2],   s[2*ks][3]);
            aP[2] = packh2(s[2*ks+1][0], s[2*ks+1][1]);
            aP[3] = packh2(s[2*ks+1][2], s[2*ks+1][3]);
            #pragma unroll
            for (int nt2=0; nt2<8; nt2++){
                uint32_t vf[4];
                ldsm4t(vf, vaBase + (uint32_t)ks*(16*AT_ROWB) + (uint32_t)nt2*32);
                mma_f16(o[2*nt2],   aP, vf[0], vf[1]);
                mma_f16(o[2*nt2+1], aP, vf[2], vf[3]);
            }
        }
    }

    // ---- epilogue: normalize + fp16 store (stride Dn for Wo GEMM) ----
    float inv0 = 1.0f/l0, inv1 = 1.0f/l1;
    size_t r0off = (rowbase + (size_t)grow0)*Dn + colb + ((lane&3)<<1);
    size_t r1off = r0off + 8*(size_t)Dn;
    #pragma unroll
    for (int nt=0; nt<16; nt++){
        *(uint32_t*)&OgH[r0off + nt*8] = packh2(o[nt][0]*inv0, o[nt][1]*inv0);
        *(uint32_t*)&OgH[r1off + nt*8] = packh2(o[nt][2]*inv1, o[nt][3]*inv1);
    }
}

// ======================= launch =============================================
extern "C" void kernel_launch(void* const* d_in, const int* in_sizes, int n_in,
                              void* d_out, int out_size) {
    const float* x  = (const float*)d_in[0];
    const int*   tp = (const int*)d_in[2];
    const float* Wq = (const float*)d_in[3];
    const float* Wk = (const float*)d_in[4];
    const float* Wv = (const float*)d_in[5];
    const float* Wo = (const float*)d_in[6];
    float* out = (float*)d_out;

    __half *xH, *wH, *OH, *QKVf;
    cudaGetSymbolAddress((void**)&xH, g_xH);
    cudaGetSymbolAddress((void**)&wH, g_wH);
    cudaGetSymbolAddress((void**)&OH, g_OH);
    cudaGetSymbolAddress((void**)&QKVf, g_QKVf);
    const size_t WS = (size_t)Dn*Dn;

    cudaFuncSetAttribute((const void*)gemm_qkv,
                         cudaFuncAttributeMaxDynamicSharedMemorySize, QG_SMEM);
    cudaFuncSetAttribute((const void*)gemm_fp16,
                         cudaFuncAttributeMaxDynamicSharedMemorySize, FG_SMEM);
    cudaFuncSetAttribute((const void*)attn_mma,
                         cudaFuncAttributeMaxDynamicSharedMemorySize, AT_SMEM);

    // fp16 conversion of x + weights, and rope tables, one launch
    conv_all<<<dim3((Dn*Dn/4 + 255)/256, 7), 256>>>(x, Wq, Wk, Wv, Wo);

    // fused QKV projection + RoPE + fp16
    gemm_qkv<<<dim3(NQKV/192, MROWS/128), 256, QG_SMEM>>>(xH, wH, tp, QKVf);

    // flash attention (fp16 MMA, KB=128)
    attn_mma<<<dim3(Ln/128, Bn*Hn), 256, AT_SMEM>>>(QKVf, OH);

    // output projection
    gemm_fp16<<<dim3(Dn/256, MROWS/128), 256, FG_SMEM>>>(OH, wH+3*WS, out);
}